// round 6
// baseline (speedup 1.0000x reference)
#include <cuda_runtime.h>
#include <cuda_fp16.h>
#include <cstdint>

// Problem constants
#define Bb 2
#define Tt 4096
#define Dd 4096
#define Hh 32
#define HKV 8
#define DH 128
#define Mrows 8192         // B*T
#define Ncols 6144         // D + 2*HKV*DH
#define Kdim 4096

// GEMM tiling (fp16 legacy mma + ldmatrix), 256 thr = 8 warps (2Mx4N), warp 64x32
#define BM 128
#define BN 128
#define BK 64
#define NKITER (Kdim / BK)            // 64
#define STAGES 3
#define A_STAGE_BYTES (BM * BK * 2)   // 16384
#define B_STAGE_BYTES (BN * BK * 2)   // 16384
#define SMEM_BYTES (STAGES * (A_STAGE_BYTES + B_STAGE_BYTES))  // 98304

#define MT (Mrows / BM)   // 64
#define NT (Ncols / BN)   // 48
#define NTILES (MT * NT)  // 3072
#define GM 16
#define GRID_GEMM 296     // 2 persistent CTAs per SM

// Scratch device globals
__device__ __half g_Ch[(size_t)Mrows * Ncols];        // GEMM result fp16 (~100 MB)
__device__ __half g_xh[(size_t)Mrows * Kdim];         // fp16 x, [M,K] row-major
__device__ __half g_Wth[(size_t)Ncols * Kdim];        // fp16 W^T, [N,K] row-major
__device__ float2 g_tab[Tt * (DH / 2)];               // RoPE (cos,sin) table

// ---------------------------------------------------------------------------
// PTX helpers
// ---------------------------------------------------------------------------
__device__ __forceinline__ void cp_async16(uint32_t dst, const void* src) {
    asm volatile("cp.async.cg.shared.global [%0], [%1], 16;\n" :: "r"(dst), "l"(src));
}
__device__ __forceinline__ void cp_commit() {
    asm volatile("cp.async.commit_group;\n" ::: "memory");
}
__device__ __forceinline__ void cp_wait1() {
    asm volatile("cp.async.wait_group 1;\n" ::: "memory");
}
__device__ __forceinline__ void ldmatrix_x4(uint32_t r[4], uint32_t addr) {
    asm volatile("ldmatrix.sync.aligned.m8n8.x4.shared.b16 {%0,%1,%2,%3}, [%4];"
                 : "=r"(r[0]), "=r"(r[1]), "=r"(r[2]), "=r"(r[3]) : "r"(addr));
}
__device__ __forceinline__ void mma_f16(float c[4], const uint32_t a[4], const uint32_t b[2]) {
    asm volatile(
        "mma.sync.aligned.m16n8k16.row.col.f32.f16.f16.f32 "
        "{%0,%1,%2,%3}, {%4,%5,%6,%7}, {%8,%9}, {%0,%1,%2,%3};"
        : "+f"(c[0]), "+f"(c[1]), "+f"(c[2]), "+f"(c[3])
        : "r"(a[0]), "r"(a[1]), "r"(a[2]), "r"(a[3]), "r"(b[0]), "r"(b[1]));
}
__device__ __forceinline__ uint32_t swz128(uint32_t off) {
    return off ^ ((off >> 3) & 0x70);
}

// ---------------------------------------------------------------------------
// Kernel 1: RoPE cos/sin table
// ---------------------------------------------------------------------------
__global__ void rope_table_kernel() {
    int idx = blockIdx.x * blockDim.x + threadIdx.x;
    if (idx >= Tt * 64) return;
    int t = idx >> 6;
    int j = idx & 63;
    double inv = exp2(-((double)(2 * j)) * (1.0 / 128.0) * 13.287712379549449);
    double a = (double)t * inv;
    double red = remainder(a, 6.283185307179586477);
    float s, c;
    sincosf((float)red, &s, &c);
    g_tab[idx] = make_float2(c, s);
}

// ---------------------------------------------------------------------------
// Kernel 2a: convert x -> fp16
// ---------------------------------------------------------------------------
__global__ void convert_x_kernel(const float* __restrict__ x) {
    size_t i = (size_t)blockIdx.x * blockDim.x + threadIdx.x;   // float4 index
    const size_t N4 = (size_t)Mrows * Kdim / 4;
    if (i >= N4) return;
    float4 v = reinterpret_cast<const float4*>(x)[i];
    __half2 h0 = make_half2(__float2half_rn(v.x), __float2half_rn(v.y));
    __half2 h1 = make_half2(__float2half_rn(v.z), __float2half_rn(v.w));
    reinterpret_cast<__half2*>(g_xh)[2 * i]     = h0;
    reinterpret_cast<__half2*>(g_xh)[2 * i + 1] = h1;
}

// ---------------------------------------------------------------------------
// Kernel 2b: transpose + convert [Wq|Wk|Wv] -> fp16 g_Wth[n][k]
// ---------------------------------------------------------------------------
__global__ void convert_w_kernel(const float* __restrict__ Wq,
                                 const float* __restrict__ Wk,
                                 const float* __restrict__ Wv) {
    __shared__ __half tile[32][34];
    const int n0 = blockIdx.x * 32;
    const int k0 = blockIdx.y * 32;
    #pragma unroll
    for (int i = 0; i < 4; i++) {
        int k = k0 + threadIdx.y + i * 8;
        int n = n0 + threadIdx.x;
        float v;
        if (n < 4096)       v = Wq[(size_t)k * 4096 + n];
        else if (n < 5120)  v = Wk[(size_t)k * 1024 + (n - 4096)];
        else                v = Wv[(size_t)k * 1024 + (n - 5120)];
        tile[threadIdx.y + i * 8][threadIdx.x] = __float2half_rn(v);
    }
    __syncthreads();
    #pragma unroll
    for (int i = 0; i < 4; i++) {
        int n = n0 + threadIdx.y + i * 8;
        int k = k0 + threadIdx.x;
        g_Wth[(size_t)n * Kdim + k] = tile[threadIdx.x][threadIdx.y + i * 8];
    }
}

// ---------------------------------------------------------------------------
// Kernel 3: persistent fp16 GEMM  C = g_xh @ g_Wth^T (ldmatrix + HMMA)
// 296 persistent CTAs, 256 thr = 8 warps (2M x 4N), warp 64x32, 3-stage cp.async
// ---------------------------------------------------------------------------
__global__ __launch_bounds__(256, 2) void gemm_kernel() {
    extern __shared__ char smem[];
    const uint32_t smem_base = (uint32_t)__cvta_generic_to_shared(smem);
    const uint32_t a_base = smem_base;                          // 3 x 16KB
    const uint32_t b_base = smem_base + STAGES * A_STAGE_BYTES; // 3 x 16KB

    const int tid = threadIdx.x;
    const int lane = tid & 31;
    const int wid = tid >> 5;
    const int warp_m = wid & 1;   // 0..1, 64 rows
    const int warp_n = wid >> 1;  // 0..3, 32 cols

    // ldmatrix lane addressing (loop-invariant parts)
    const int a_row = warp_m * 64 + (lane & 15);                      // + mi*16
    const int a_ch  = lane >> 4;                                      // + ks*2
    const int b_row = warp_n * 32 + (lane & 7) + ((lane >> 4) << 3);  // + ng*16
    const int b_ch  = (lane >> 3) & 1;                                // + ks*2

    // ---- load cursor (flattened across tiles) ----
    int lt_tile = blockIdx.x;   // tile index being loaded
    int lt_k = 0;               // k-tile within it
    int islot = 0;              // smem slot to fill next

    auto issue_next = [&]() {
        int t = (lt_tile < NTILES) ? lt_tile : (int)blockIdx.x;   // dummy reload if done
        int k = (lt_tile < NTILES) ? lt_k : 0;
        int group = t / (GM * NT);
        int rem = t % (GM * NT);
        const int m0 = (group * GM + (rem % GM)) * BM;
        const int n0 = (rem / GM) * BN;
        const int k0 = k * BK;
        const uint32_t a_dst = a_base + islot * A_STAGE_BYTES;
        const uint32_t b_dst = b_base + islot * B_STAGE_BYTES;
        const __half* a_src = g_xh + (size_t)m0 * Kdim + k0;
        const __half* b_src = g_Wth + (size_t)n0 * Kdim + k0;
        #pragma unroll
        for (int i = 0; i < 4; i++) {          // A: 1024 16B-chunks / 256 thr
            int idx = tid + i * 256;
            int row = idx >> 3;
            int kq = idx & 7;
            cp_async16(a_dst + swz128(row * 128 + kq * 16),
                       a_src + (size_t)row * Kdim + kq * 8);
        }
        #pragma unroll
        for (int i = 0; i < 4; i++) {          // B: 1024 16B-chunks / 256 thr
            int idx = tid + i * 256;
            int row = idx >> 3;
            int kq = idx & 7;
            cp_async16(b_dst + swz128(row * 128 + kq * 16),
                       b_src + (size_t)row * Kdim + kq * 8);
        }
        cp_commit();
        islot = (islot == STAGES - 1) ? 0 : islot + 1;
        if (++lt_k == NKITER) { lt_k = 0; lt_tile += gridDim.x; }
    };

    auto load_frags = [&](uint32_t A_s, uint32_t B_s, int ks,
                          uint32_t (&a)[4][4], uint32_t (&b)[2][4]) {
        #pragma unroll
        for (int mi = 0; mi < 4; mi++)
            ldmatrix_x4(a[mi], A_s + swz128((a_row + mi * 16) * 128 +
                                            (ks * 2 + a_ch) * 16));
        #pragma unroll
        for (int ng = 0; ng < 2; ng++)
            ldmatrix_x4(b[ng], B_s + swz128((b_row + ng * 16) * 128 +
                                            (ks * 2 + b_ch) * 16));
    };

    float acc[4][4][4];

    // prologue: 2 stages in flight
    issue_next();
    issue_next();
    int cur = 0;

    #pragma unroll 1
    for (int tile = blockIdx.x; tile < NTILES; tile += gridDim.x) {
        int group = tile / (GM * NT);
        int rem = tile % (GM * NT);
        const int m0 = (group * GM + (rem % GM)) * BM;
        const int n0 = (rem / GM) * BN;

        #pragma unroll
        for (int i = 0; i < 4; i++)
            #pragma unroll
            for (int j = 0; j < 4; j++)
                #pragma unroll
                for (int r = 0; r < 4; r++)
                    acc[i][j][r] = 0.0f;

        #pragma unroll 1
        for (int it = 0; it < NKITER; it++) {
            cp_wait1();
            __syncthreads();
            const uint32_t A_s = a_base + cur * A_STAGE_BYTES;
            const uint32_t B_s = b_base + cur * B_STAGE_BYTES;

            uint32_t a[4][4], b[2][4];
            // ks=0 fragments FIRST (start tensor pipe early), then prefetch
            load_frags(A_s, B_s, 0, a, b);
            issue_next();
            #pragma unroll
            for (int mi = 0; mi < 4; mi++) {
                #pragma unroll
                for (int ng = 0; ng < 2; ng++) {
                    mma_f16(acc[mi][ng * 2],     a[mi], &b[ng][0]);
                    mma_f16(acc[mi][ng * 2 + 1], a[mi], &b[ng][2]);
                }
            }
            #pragma unroll
            for (int ks = 1; ks < 4; ks++) {
                load_frags(A_s, B_s, ks, a, b);
                #pragma unroll
                for (int mi = 0; mi < 4; mi++) {
                    #pragma unroll
                    for (int ng = 0; ng < 2; ng++) {
                        mma_f16(acc[mi][ng * 2],     a[mi], &b[ng][0]);
                        mma_f16(acc[mi][ng * 2 + 1], a[mi], &b[ng][2]);
                    }
                }
            }
            cur = (cur == STAGES - 1) ? 0 : cur + 1;
        }

        // store accumulators (fp16)
        const int nbase = n0 + warp_n * 32;
        #pragma unroll
        for (int mi = 0; mi < 4; mi++) {
            int row = m0 + warp_m * 64 + mi * 16 + (lane >> 2);
            #pragma unroll
            for (int ni = 0; ni < 4; ni++) {
                int col = nbase + ni * 8 + (lane & 3) * 2;
                __half* p = g_Ch + (size_t)row * Ncols + col;
                *reinterpret_cast<__half2*>(p) =
                    make_half2(__float2half_rn(acc[mi][ni][0]),
                               __float2half_rn(acc[mi][ni][1]));
                *reinterpret_cast<__half2*>(p + (size_t)8 * Ncols) =
                    make_half2(__float2half_rn(acc[mi][ni][2]),
                               __float2half_rn(acc[mi][ni][3]));
            }
        }
    }
}

// ---------------------------------------------------------------------------
// Kernel 4: per-token epilogue — rmsnorm(q,k), gamma, RoPE, transpose, repeat
// ---------------------------------------------------------------------------
__global__ __launch_bounds__(256) void epilogue_kernel(
    const float* __restrict__ gq,
    const float* __restrict__ gk,
    float* __restrict__ out)
{
    const int bt = blockIdx.x;
    const int b = bt >> 12;
    const int t = bt & 4095;
    const __half* row = g_Ch + (size_t)bt * Ncols;
    const int tid = threadIdx.x;

    float2 qv[8], kv2[2], vvp[2];
    float ssq_q = 0.0f, ssq_k = 0.0f;
    #pragma unroll
    for (int i = 0; i < 8; i++) {
        int p = tid + i * 256;
        qv[i] = __half22float2(*reinterpret_cast<const __half2*>(row + 2 * p));
        ssq_q += qv[i].x * qv[i].x + qv[i].y * qv[i].y;
    }
    #pragma unroll
    for (int i = 0; i < 2; i++) {
        int p = tid + i * 256;
        kv2[i] = __half22float2(*reinterpret_cast<const __half2*>(row + 4096 + 2 * p));
        ssq_k += kv2[i].x * kv2[i].x + kv2[i].y * kv2[i].y;
    }
    {
        const __half2* vp = reinterpret_cast<const __half2*>(row + 5120 + tid * 4);
        vvp[0] = __half22float2(vp[0]);
        vvp[1] = __half22float2(vp[1]);
    }

    __shared__ float redq[256], redk[256];
    redq[tid] = ssq_q;
    redk[tid] = ssq_k;
    __syncthreads();
    #pragma unroll
    for (int s = 128; s > 0; s >>= 1) {
        if (tid < s) {
            redq[tid] += redq[tid + s];
            redk[tid] += redk[tid + s];
        }
        __syncthreads();
    }
    const float rs_q = rsqrtf(redq[0] * (1.0f / 4096.0f) + 1e-5f);
    const float rs_k = rsqrtf(redk[0] * (1.0f / 1024.0f) + 1e-5f);

    const float2* tab = g_tab + t * 64;
    float* outq = out;
    float* outk = out + (size_t)33554432;
    float* outv = out + (size_t)67108864;

    #pragma unroll
    for (int i = 0; i < 8; i++) {
        int p = tid + i * 256;
        int h = p >> 6;
        int j = p & 63;
        float2 cs = tab[j];
        float x1 = qv[i].x * rs_q * gq[2 * p];
        float x2 = qv[i].y * rs_q * gq[2 * p + 1];
        float2 r = make_float2(x1 * cs.x - x2 * cs.y, x1 * cs.y + x2 * cs.x);
        *reinterpret_cast<float2*>(
            outq + (((size_t)(b * Hh + h) * Tt + t) * DH + 2 * j)) = r;
    }
    #pragma unroll
    for (int i = 0; i < 2; i++) {
        int p = tid + i * 256;
        int kh = p >> 6;
        int j = p & 63;
        float2 cs = tab[j];
        float x1 = kv2[i].x * rs_k * gk[2 * p];
        float x2 = kv2[i].y * rs_k * gk[2 * p + 1];
        float2 r = make_float2(x1 * cs.x - x2 * cs.y, x1 * cs.y + x2 * cs.x);
        #pragma unroll
        for (int rr = 0; rr < 4; rr++) {
            int h = kh * 4 + rr;
            *reinterpret_cast<float2*>(
                outk + (((size_t)(b * Hh + h) * Tt + t) * DH + 2 * j)) = r;
        }
    }
    {
        int d = (tid * 4) & 127;
        int kh = tid >> 5;
        float4 v4 = make_float4(vvp[0].x, vvp[0].y, vvp[1].x, vvp[1].y);
        #pragma unroll
        for (int rr = 0; rr < 4; rr++) {
            int h = kh * 4 + rr;
            *reinterpret_cast<float4*>(
                outv + (((size_t)(b * Hh + h) * Tt + t) * DH + d)) = v4;
        }
    }
}

// ---------------------------------------------------------------------------
extern "C" void kernel_launch(void* const* d_in, const int* in_sizes, int n_in,
                              void* d_out, int out_size)
{
    const float* x  = (const float*)d_in[0];
    const float* Wq = (const float*)d_in[1];
    const float* Wk = (const float*)d_in[2];
    const float* Wv = (const float*)d_in[3];
    const float* gq = (const float*)d_in[4];
    const float* gk = (const float*)d_in[5];
    float* out = (float*)d_out;

    cudaFuncSetAttribute(gemm_kernel,
                         cudaFuncAttributeMaxDynamicSharedMemorySize, SMEM_BYTES);

    rope_table_kernel<<<(Tt * 64 + 255) / 256, 256>>>();
    convert_x_kernel<<<(int)(((size_t)Mrows * Kdim / 4 + 255) / 256), 256>>>(x);
    convert_w_kernel<<<dim3(Ncols / 32, Kdim / 32), dim3(32, 8)>>>(Wq, Wk, Wv);
    gemm_kernel<<<GRID_GEMM, 256, SMEM_BYTES>>>();
    epilogue_kernel<<<Mrows, 256>>>(gq, gk, out);
}

// round 7
// speedup vs baseline: 1.0726x; 1.0726x over previous
#include <cuda_runtime.h>
#include <cuda_fp16.h>
#include <cstdint>

// Problem constants
#define Bb 2
#define Tt 4096
#define Dd 4096
#define Hh 32
#define HKV 8
#define DH 128
#define Mrows 8192         // B*T
#define Ncols 6144         // D + 2*HKV*DH
#define Kdim 4096

// GEMM tiling (fp16 legacy mma + ldmatrix), 256 thr = 8 warps (2Mx4N), warp 64x32
#define BM 128
#define BN 128
#define BK 64
#define NKITER (Kdim / BK)            // 64
#define STAGES 3
#define A_STAGE_BYTES (BM * BK * 2)   // 16384
#define B_STAGE_BYTES (BN * BK * 2)   // 16384
#define SMEM_BYTES (STAGES * (A_STAGE_BYTES + B_STAGE_BYTES))  // 98304

#define MT (Mrows / BM)   // 64
#define NT (Ncols / BN)   // 48
#define GM 16

// Scratch device globals
__device__ __half g_Ch[(size_t)Mrows * Ncols];        // GEMM result fp16 (~100 MB)
__device__ __half g_xh[(size_t)Mrows * Kdim];         // fp16 x, [M,K] row-major
__device__ __half g_Wth[(size_t)Ncols * Kdim];        // fp16 W^T, [N,K] row-major
__device__ float2 g_tab[Tt * (DH / 2)];               // RoPE (cos,sin) table

// ---------------------------------------------------------------------------
// PTX helpers
// ---------------------------------------------------------------------------
__device__ __forceinline__ void cp_async16(uint32_t dst, const void* src) {
    asm volatile("cp.async.cg.shared.global [%0], [%1], 16;\n" :: "r"(dst), "l"(src));
}
__device__ __forceinline__ void cp_commit() {
    asm volatile("cp.async.commit_group;\n" ::: "memory");
}
__device__ __forceinline__ void cp_wait1() {
    asm volatile("cp.async.wait_group 1;\n" ::: "memory");
}
__device__ __forceinline__ void ldmatrix_x4(uint32_t r[4], uint32_t addr) {
    asm volatile("ldmatrix.sync.aligned.m8n8.x4.shared.b16 {%0,%1,%2,%3}, [%4];"
                 : "=r"(r[0]), "=r"(r[1]), "=r"(r[2]), "=r"(r[3]) : "r"(addr));
}
__device__ __forceinline__ void mma_f16(float c[4], const uint32_t a[4], const uint32_t b[2]) {
    asm volatile(
        "mma.sync.aligned.m16n8k16.row.col.f32.f16.f16.f32 "
        "{%0,%1,%2,%3}, {%4,%5,%6,%7}, {%8,%9}, {%0,%1,%2,%3};"
        : "+f"(c[0]), "+f"(c[1]), "+f"(c[2]), "+f"(c[3])
        : "r"(a[0]), "r"(a[1]), "r"(a[2]), "r"(a[3]), "r"(b[0]), "r"(b[1]));
}
__device__ __forceinline__ uint32_t swz128(uint32_t off) {
    return off ^ ((off >> 3) & 0x70);
}

// ---------------------------------------------------------------------------
// Kernel 1: RoPE cos/sin table
// ---------------------------------------------------------------------------
__global__ void rope_table_kernel() {
    int idx = blockIdx.x * blockDim.x + threadIdx.x;
    if (idx >= Tt * 64) return;
    int t = idx >> 6;
    int j = idx & 63;
    double inv = exp2(-((double)(2 * j)) * (1.0 / 128.0) * 13.287712379549449);
    double a = (double)t * inv;
    double red = remainder(a, 6.283185307179586477);
    float s, c;
    sincosf((float)red, &s, &c);
    g_tab[idx] = make_float2(c, s);
}

// ---------------------------------------------------------------------------
// Kernel 2a: convert x -> fp16
// ---------------------------------------------------------------------------
__global__ void convert_x_kernel(const float* __restrict__ x) {
    size_t i = (size_t)blockIdx.x * blockDim.x + threadIdx.x;   // float4 index
    const size_t N4 = (size_t)Mrows * Kdim / 4;
    if (i >= N4) return;
    float4 v = reinterpret_cast<const float4*>(x)[i];
    __half2 h0 = make_half2(__float2half_rn(v.x), __float2half_rn(v.y));
    __half2 h1 = make_half2(__float2half_rn(v.z), __float2half_rn(v.w));
    reinterpret_cast<__half2*>(g_xh)[2 * i]     = h0;
    reinterpret_cast<__half2*>(g_xh)[2 * i + 1] = h1;
}

// ---------------------------------------------------------------------------
// Kernel 2b: transpose + convert [Wq|Wk|Wv] -> fp16 g_Wth[n][k]
// ---------------------------------------------------------------------------
__global__ void convert_w_kernel(const float* __restrict__ Wq,
                                 const float* __restrict__ Wk,
                                 const float* __restrict__ Wv) {
    __shared__ __half tile[32][34];
    const int n0 = blockIdx.x * 32;
    const int k0 = blockIdx.y * 32;
    #pragma unroll
    for (int i = 0; i < 4; i++) {
        int k = k0 + threadIdx.y + i * 8;
        int n = n0 + threadIdx.x;
        float v;
        if (n < 4096)       v = Wq[(size_t)k * 4096 + n];
        else if (n < 5120)  v = Wk[(size_t)k * 1024 + (n - 4096)];
        else                v = Wv[(size_t)k * 1024 + (n - 5120)];
        tile[threadIdx.y + i * 8][threadIdx.x] = __float2half_rn(v);
    }
    __syncthreads();
    #pragma unroll
    for (int i = 0; i < 4; i++) {
        int n = n0 + threadIdx.y + i * 8;
        int k = k0 + threadIdx.x;
        g_Wth[(size_t)n * Kdim + k] = tile[threadIdx.x][threadIdx.y + i * 8];
    }
}

// ---------------------------------------------------------------------------
// Kernel 3: fp16 GEMM  C = g_xh @ g_Wth^T   (ldmatrix + HMMA)
// 3072 CTAs (64 M x 48 N, GROUP_M=16), 256 thr = 8 warps (2M x 4N), warp 64x32
// ---------------------------------------------------------------------------
__global__ __launch_bounds__(256, 2) void gemm_kernel() {
    extern __shared__ char smem[];
    const uint32_t smem_base = (uint32_t)__cvta_generic_to_shared(smem);
    const uint32_t a_base = smem_base;                          // 3 x 16KB
    const uint32_t b_base = smem_base + STAGES * A_STAGE_BYTES; // 3 x 16KB

    int gid = blockIdx.x;
    int group = gid / (GM * NT);
    int rem = gid % (GM * NT);
    const int mt = group * GM + (rem % GM);
    const int nt = rem / GM;
    const int m0 = mt * BM;
    const int n0 = nt * BN;

    const int tid = threadIdx.x;
    const int lane = tid & 31;
    const int wid = tid >> 5;
    const int warp_m = wid & 1;   // 0..1, 64 rows
    const int warp_n = wid >> 1;  // 0..3, 32 cols

    float acc[4][4][4];
    #pragma unroll
    for (int i = 0; i < 4; i++)
        #pragma unroll
        for (int j = 0; j < 4; j++)
            #pragma unroll
            for (int r = 0; r < 4; r++)
                acc[i][j][r] = 0.0f;

    auto issue = [&](int ktile, int slot) {
        const int k0 = ktile * BK;
        const uint32_t a_dst = a_base + slot * A_STAGE_BYTES;
        const uint32_t b_dst = b_base + slot * B_STAGE_BYTES;
        const __half* a_src = g_xh + (size_t)m0 * Kdim + k0;
        const __half* b_src = g_Wth + (size_t)n0 * Kdim + k0;
        #pragma unroll
        for (int i = 0; i < 4; i++) {
            int idx = tid + i * 256;       // 0..1023
            int row = idx >> 3;            // 0..127
            int kq = idx & 7;              // 16B chunk within 128B row
            cp_async16(a_dst + swz128(row * 128 + kq * 16),
                       a_src + (size_t)row * Kdim + kq * 8);
        }
        #pragma unroll
        for (int i = 0; i < 4; i++) {
            int idx = tid + i * 256;
            int row = idx >> 3;
            int kq = idx & 7;
            cp_async16(b_dst + swz128(row * 128 + kq * 16),
                       b_src + (size_t)row * Kdim + kq * 8);
        }
        cp_commit();
    };

    issue(0, 0);
    issue(1, 1);

    // ldmatrix lane addressing
    const int a_row = warp_m * 64 + (lane & 15);                      // + mi*16
    const int a_ch  = lane >> 4;                                      // + ks*2
    const int b_row = warp_n * 32 + (lane & 7) + ((lane >> 4) << 3);  // + ng*16
    const int b_ch  = (lane >> 3) & 1;                                // + ks*2

    #pragma unroll 1
    for (int it = 0; it < NKITER; it++) {
        const int slot = it % STAGES;
        cp_wait1();
        __syncthreads();

        const uint32_t A_s = a_base + slot * A_STAGE_BYTES;
        const uint32_t B_s = b_base + slot * B_STAGE_BYTES;

        // ks=0 fragments FIRST so the tensor pipe restarts immediately,
        // then the next-stage copy burst, then the remaining k-steps.
        uint32_t a[4][4], b[2][4];
        #pragma unroll
        for (int mi = 0; mi < 4; mi++)
            ldmatrix_x4(a[mi], A_s + swz128((a_row + mi * 16) * 128 + a_ch * 16));
        #pragma unroll
        for (int ng = 0; ng < 2; ng++)
            ldmatrix_x4(b[ng], B_s + swz128((b_row + ng * 16) * 128 + b_ch * 16));

        {
            int lt = it + 2;
            if (lt > NKITER - 1) lt = NKITER - 1;
            issue(lt, (it + 2) % STAGES);
        }

        #pragma unroll
        for (int mi = 0; mi < 4; mi++) {
            #pragma unroll
            for (int ng = 0; ng < 2; ng++) {
                mma_f16(acc[mi][ng * 2],     a[mi], &b[ng][0]);
                mma_f16(acc[mi][ng * 2 + 1], a[mi], &b[ng][2]);
            }
        }

        #pragma unroll
        for (int ks = 1; ks < 4; ks++) {
            #pragma unroll
            for (int mi = 0; mi < 4; mi++)
                ldmatrix_x4(a[mi], A_s + swz128((a_row + mi * 16) * 128 +
                                                (ks * 2 + a_ch) * 16));
            #pragma unroll
            for (int ng = 0; ng < 2; ng++)
                ldmatrix_x4(b[ng], B_s + swz128((b_row + ng * 16) * 128 +
                                                (ks * 2 + b_ch) * 16));
            #pragma unroll
            for (int mi = 0; mi < 4; mi++) {
                #pragma unroll
                for (int ng = 0; ng < 2; ng++) {
                    mma_f16(acc[mi][ng * 2],     a[mi], &b[ng][0]);
                    mma_f16(acc[mi][ng * 2 + 1], a[mi], &b[ng][2]);
                }
            }
        }
    }

    // write accumulators to fp16 scratch C
    const int nbase = n0 + warp_n * 32;
    #pragma unroll
    for (int mi = 0; mi < 4; mi++) {
        int row = m0 + warp_m * 64 + mi * 16 + (lane >> 2);
        #pragma unroll
        for (int ni = 0; ni < 4; ni++) {
            int col = nbase + ni * 8 + (lane & 3) * 2;
            __half* p = g_Ch + (size_t)row * Ncols + col;
            *reinterpret_cast<__half2*>(p) =
                make_half2(__float2half_rn(acc[mi][ni][0]),
                           __float2half_rn(acc[mi][ni][1]));
            *reinterpret_cast<__half2*>(p + (size_t)8 * Ncols) =
                make_half2(__float2half_rn(acc[mi][ni][2]),
                           __float2half_rn(acc[mi][ni][3]));
        }
    }
}

// ---------------------------------------------------------------------------
// Kernel 4: per-token epilogue — rmsnorm(q,k), gamma, RoPE, transpose, repeat
// ---------------------------------------------------------------------------
__global__ __launch_bounds__(256) void epilogue_kernel(
    const float* __restrict__ gq,
    const float* __restrict__ gk,
    float* __restrict__ out)
{
    const int bt = blockIdx.x;
    const int b = bt >> 12;
    const int t = bt & 4095;
    const __half* row = g_Ch + (size_t)bt * Ncols;
    const int tid = threadIdx.x;

    float2 qv[8], kv2[2], vvp[2];
    float ssq_q = 0.0f, ssq_k = 0.0f;
    #pragma unroll
    for (int i = 0; i < 8; i++) {
        int p = tid + i * 256;
        qv[i] = __half22float2(*reinterpret_cast<const __half2*>(row + 2 * p));
        ssq_q += qv[i].x * qv[i].x + qv[i].y * qv[i].y;
    }
    #pragma unroll
    for (int i = 0; i < 2; i++) {
        int p = tid + i * 256;
        kv2[i] = __half22float2(*reinterpret_cast<const __half2*>(row + 4096 + 2 * p));
        ssq_k += kv2[i].x * kv2[i].x + kv2[i].y * kv2[i].y;
    }
    {
        const __half2* vp = reinterpret_cast<const __half2*>(row + 5120 + tid * 4);
        vvp[0] = __half22float2(vp[0]);
        vvp[1] = __half22float2(vp[1]);
    }

    __shared__ float redq[256], redk[256];
    redq[tid] = ssq_q;
    redk[tid] = ssq_k;
    __syncthreads();
    #pragma unroll
    for (int s = 128; s > 0; s >>= 1) {
        if (tid < s) {
            redq[tid] += redq[tid + s];
            redk[tid] += redk[tid + s];
        }
        __syncthreads();
    }
    const float rs_q = rsqrtf(redq[0] * (1.0f / 4096.0f) + 1e-5f);
    const float rs_k = rsqrtf(redk[0] * (1.0f / 1024.0f) + 1e-5f);

    const float2* tab = g_tab + t * 64;
    float* outq = out;
    float* outk = out + (size_t)33554432;
    float* outv = out + (size_t)67108864;

    #pragma unroll
    for (int i = 0; i < 8; i++) {
        int p = tid + i * 256;
        int h = p >> 6;
        int j = p & 63;
        float2 cs = tab[j];
        float x1 = qv[i].x * rs_q * gq[2 * p];
        float x2 = qv[i].y * rs_q * gq[2 * p + 1];
        float2 r = make_float2(x1 * cs.x - x2 * cs.y, x1 * cs.y + x2 * cs.x);
        *reinterpret_cast<float2*>(
            outq + (((size_t)(b * Hh + h) * Tt + t) * DH + 2 * j)) = r;
    }
    #pragma unroll
    for (int i = 0; i < 2; i++) {
        int p = tid + i * 256;
        int kh = p >> 6;
        int j = p & 63;
        float2 cs = tab[j];
        float x1 = kv2[i].x * rs_k * gk[2 * p];
        float x2 = kv2[i].y * rs_k * gk[2 * p + 1];
        float2 r = make_float2(x1 * cs.x - x2 * cs.y, x1 * cs.y + x2 * cs.x);
        #pragma unroll
        for (int rr = 0; rr < 4; rr++) {
            int h = kh * 4 + rr;
            *reinterpret_cast<float2*>(
                outk + (((size_t)(b * Hh + h) * Tt + t) * DH + 2 * j)) = r;
        }
    }
    {
        int d = (tid * 4) & 127;
        int kh = tid >> 5;
        float4 v4 = make_float4(vvp[0].x, vvp[0].y, vvp[1].x, vvp[1].y);
        #pragma unroll
        for (int rr = 0; rr < 4; rr++) {
            int h = kh * 4 + rr;
            *reinterpret_cast<float4*>(
                outv + (((size_t)(b * Hh + h) * Tt + t) * DH + d)) = v4;
        }
    }
}

// ---------------------------------------------------------------------------
extern "C" void kernel_launch(void* const* d_in, const int* in_sizes, int n_in,
                              void* d_out, int out_size)
{
    const float* x  = (const float*)d_in[0];
    const float* Wq = (const float*)d_in[1];
    const float* Wk = (const float*)d_in[2];
    const float* Wv = (const float*)d_in[3];
    const float* gq = (const float*)d_in[4];
    const float* gk = (const float*)d_in[5];
    float* out = (float*)d_out;

    cudaFuncSetAttribute(gemm_kernel,
                         cudaFuncAttributeMaxDynamicSharedMemorySize, SMEM_BYTES);

    rope_table_kernel<<<(Tt * 64 + 255) / 256, 256>>>();
    convert_x_kernel<<<(int)(((size_t)Mrows * Kdim / 4 + 255) / 256), 256>>>(x);
    convert_w_kernel<<<dim3(Ncols / 32, Kdim / 32), dim3(32, 8)>>>(Wq, Wk, Wv);
    gemm_kernel<<<MT * NT, 256, SMEM_BYTES>>>();
    epilogue_kernel<<<Mrows, 256>>>(gq, gk, out);
}

// round 8
// speedup vs baseline: 1.0894x; 1.0157x over previous
#include <cuda_runtime.h>
#include <cuda_fp16.h>
#include <cstdint>

// Problem constants
#define Bb 2
#define Tt 4096
#define Dd 4096
#define Hh 32
#define HKV 8
#define DH 128
#define Mrows 8192         // B*T
#define Ncols 6144         // D + 2*HKV*DH
#define Kdim 4096

// GEMM tiling (fp16 legacy mma + ldmatrix), 256 thr = 8 warps (2Mx4N), warp 64x32
#define BM 128
#define BN 128
#define BK 64
#define NKITER (Kdim / BK)            // 64
#define STAGES 3
#define A_STAGE_BYTES (BM * BK * 2)   // 16384
#define B_STAGE_BYTES (BN * BK * 2)   // 16384
#define SMEM_BYTES (STAGES * (A_STAGE_BYTES + B_STAGE_BYTES))  // 98304

#define MT (Mrows / BM)   // 64
#define NT (Ncols / BN)   // 48
#define GM 16

// Scratch device globals
__device__ __half g_Ch[(size_t)Mrows * Ncols];        // GEMM result fp16 (~100 MB)
__device__ __half g_xh[(size_t)Mrows * Kdim];         // fp16 x, [M,K] row-major
__device__ __half g_Wth[(size_t)Ncols * Kdim];        // fp16 W^T, [N,K] row-major
__device__ float2 g_tab[Tt * (DH / 2)];               // RoPE (cos,sin) table

// ---------------------------------------------------------------------------
// PTX helpers
// ---------------------------------------------------------------------------
__device__ __forceinline__ void cp_async16(uint32_t dst, const void* src) {
    asm volatile("cp.async.cg.shared.global [%0], [%1], 16;\n" :: "r"(dst), "l"(src));
}
__device__ __forceinline__ void cp_commit() {
    asm volatile("cp.async.commit_group;\n" ::: "memory");
}
__device__ __forceinline__ void cp_wait1() {
    asm volatile("cp.async.wait_group 1;\n" ::: "memory");
}
__device__ __forceinline__ void ldmatrix_x4(uint32_t r[4], uint32_t addr) {
    asm volatile("ldmatrix.sync.aligned.m8n8.x4.shared.b16 {%0,%1,%2,%3}, [%4];"
                 : "=r"(r[0]), "=r"(r[1]), "=r"(r[2]), "=r"(r[3]) : "r"(addr));
}
__device__ __forceinline__ void mma_f16(float c[4], const uint32_t a[4], const uint32_t b[2]) {
    asm volatile(
        "mma.sync.aligned.m16n8k16.row.col.f32.f16.f16.f32 "
        "{%0,%1,%2,%3}, {%4,%5,%6,%7}, {%8,%9}, {%0,%1,%2,%3};"
        : "+f"(c[0]), "+f"(c[1]), "+f"(c[2]), "+f"(c[3])
        : "r"(a[0]), "r"(a[1]), "r"(a[2]), "r"(a[3]), "r"(b[0]), "r"(b[1]));
}
__device__ __forceinline__ uint32_t swz128(uint32_t off) {
    return off ^ ((off >> 3) & 0x70);
}

// ---------------------------------------------------------------------------
// Kernel 1: RoPE cos/sin table
// ---------------------------------------------------------------------------
__global__ void rope_table_kernel() {
    int idx = blockIdx.x * blockDim.x + threadIdx.x;
    if (idx >= Tt * 64) return;
    int t = idx >> 6;
    int j = idx & 63;
    double inv = exp2(-((double)(2 * j)) * (1.0 / 128.0) * 13.287712379549449);
    double a = (double)t * inv;
    double red = remainder(a, 6.283185307179586477);
    float s, c;
    sincosf((float)red, &s, &c);
    g_tab[idx] = make_float2(c, s);
}

// ---------------------------------------------------------------------------
// Kernel 2a: convert x -> fp16
// ---------------------------------------------------------------------------
__global__ void convert_x_kernel(const float* __restrict__ x) {
    size_t i = (size_t)blockIdx.x * blockDim.x + threadIdx.x;   // float4 index
    const size_t N4 = (size_t)Mrows * Kdim / 4;
    if (i >= N4) return;
    float4 v = reinterpret_cast<const float4*>(x)[i];
    __half2 h0 = make_half2(__float2half_rn(v.x), __float2half_rn(v.y));
    __half2 h1 = make_half2(__float2half_rn(v.z), __float2half_rn(v.w));
    reinterpret_cast<__half2*>(g_xh)[2 * i]     = h0;
    reinterpret_cast<__half2*>(g_xh)[2 * i + 1] = h1;
}

// ---------------------------------------------------------------------------
// Kernel 2b: transpose + convert [Wq|Wk|Wv] -> fp16 g_Wth[n][k]
// ---------------------------------------------------------------------------
__global__ void convert_w_kernel(const float* __restrict__ Wq,
                                 const float* __restrict__ Wk,
                                 const float* __restrict__ Wv) {
    __shared__ __half tile[32][34];
    const int n0 = blockIdx.x * 32;
    const int k0 = blockIdx.y * 32;
    #pragma unroll
    for (int i = 0; i < 4; i++) {
        int k = k0 + threadIdx.y + i * 8;
        int n = n0 + threadIdx.x;
        float v;
        if (n < 4096)       v = Wq[(size_t)k * 4096 + n];
        else if (n < 5120)  v = Wk[(size_t)k * 1024 + (n - 4096)];
        else                v = Wv[(size_t)k * 1024 + (n - 5120)];
        tile[threadIdx.y + i * 8][threadIdx.x] = __float2half_rn(v);
    }
    __syncthreads();
    #pragma unroll
    for (int i = 0; i < 4; i++) {
        int n = n0 + threadIdx.y + i * 8;
        int k = k0 + threadIdx.x;
        g_Wth[(size_t)n * Kdim + k] = tile[threadIdx.x][threadIdx.y + i * 8];
    }
}

// ---------------------------------------------------------------------------
// Kernel 3: fp16 GEMM  C = g_xh @ g_Wth^T   (ldmatrix + HMMA)  [R4 loop order]
// 3072 CTAs (64 M x 48 N, GROUP_M=16), 256 thr = 8 warps (2M x 4N), warp 64x32
// ---------------------------------------------------------------------------
__global__ __launch_bounds__(256, 2) void gemm_kernel() {
    extern __shared__ char smem[];
    const uint32_t smem_base = (uint32_t)__cvta_generic_to_shared(smem);
    const uint32_t a_base = smem_base;                          // 3 x 16KB
    const uint32_t b_base = smem_base + STAGES * A_STAGE_BYTES; // 3 x 16KB

    int gid = blockIdx.x;
    int group = gid / (GM * NT);
    int rem = gid % (GM * NT);
    const int mt = group * GM + (rem % GM);
    const int nt = rem / GM;
    const int m0 = mt * BM;
    const int n0 = nt * BN;

    const int tid = threadIdx.x;
    const int lane = tid & 31;
    const int wid = tid >> 5;
    const int warp_m = wid & 1;   // 0..1, 64 rows
    const int warp_n = wid >> 1;  // 0..3, 32 cols

    float acc[4][4][4];
    #pragma unroll
    for (int i = 0; i < 4; i++)
        #pragma unroll
        for (int j = 0; j < 4; j++)
            #pragma unroll
            for (int r = 0; r < 4; r++)
                acc[i][j][r] = 0.0f;

    auto issue = [&](int ktile, int slot) {
        const int k0 = ktile * BK;
        const uint32_t a_dst = a_base + slot * A_STAGE_BYTES;
        const uint32_t b_dst = b_base + slot * B_STAGE_BYTES;
        const __half* a_src = g_xh + (size_t)m0 * Kdim + k0;
        const __half* b_src = g_Wth + (size_t)n0 * Kdim + k0;
        #pragma unroll
        for (int i = 0; i < 4; i++) {
            int idx = tid + i * 256;       // 0..1023
            int row = idx >> 3;            // 0..127
            int kq = idx & 7;              // 16B chunk within 128B row
            cp_async16(a_dst + swz128(row * 128 + kq * 16),
                       a_src + (size_t)row * Kdim + kq * 8);
        }
        #pragma unroll
        for (int i = 0; i < 4; i++) {
            int idx = tid + i * 256;
            int row = idx >> 3;
            int kq = idx & 7;
            cp_async16(b_dst + swz128(row * 128 + kq * 16),
                       b_src + (size_t)row * Kdim + kq * 8);
        }
        cp_commit();
    };

    issue(0, 0);
    issue(1, 1);

    // ldmatrix lane addressing
    const int a_row = warp_m * 64 + (lane & 15);                      // + mi*16
    const int a_ch  = lane >> 4;                                      // + ks*2
    const int b_row = warp_n * 32 + (lane & 7) + ((lane >> 4) << 3);  // + ng*16
    const int b_ch  = (lane >> 3) & 1;                                // + ks*2

    #pragma unroll 1
    for (int it = 0; it < NKITER; it++) {
        const int slot = it % STAGES;
        cp_wait1();
        __syncthreads();

        {
            int lt = it + 2;
            if (lt > NKITER - 1) lt = NKITER - 1;
            issue(lt, (it + 2) % STAGES);
        }

        const uint32_t A_s = a_base + slot * A_STAGE_BYTES;
        const uint32_t B_s = b_base + slot * B_STAGE_BYTES;

        #pragma unroll
        for (int ks = 0; ks < 4; ks++) {
            uint32_t a[4][4], b[2][4];
            #pragma unroll
            for (int mi = 0; mi < 4; mi++)
                ldmatrix_x4(a[mi], A_s + swz128((a_row + mi * 16) * 128 +
                                                (ks * 2 + a_ch) * 16));
            #pragma unroll
            for (int ng = 0; ng < 2; ng++)
                ldmatrix_x4(b[ng], B_s + swz128((b_row + ng * 16) * 128 +
                                                (ks * 2 + b_ch) * 16));
            #pragma unroll
            for (int mi = 0; mi < 4; mi++) {
                #pragma unroll
                for (int ng = 0; ng < 2; ng++) {
                    mma_f16(acc[mi][ng * 2],     a[mi], &b[ng][0]);
                    mma_f16(acc[mi][ng * 2 + 1], a[mi], &b[ng][2]);
                }
            }
        }
    }

    // write accumulators to fp16 scratch C
    const int nbase = n0 + warp_n * 32;
    #pragma unroll
    for (int mi = 0; mi < 4; mi++) {
        int row = m0 + warp_m * 64 + mi * 16 + (lane >> 2);
        #pragma unroll
        for (int ni = 0; ni < 4; ni++) {
            int col = nbase + ni * 8 + (lane & 3) * 2;
            __half* p = g_Ch + (size_t)row * Ncols + col;
            *reinterpret_cast<__half2*>(p) =
                make_half2(__float2half_rn(acc[mi][ni][0]),
                           __float2half_rn(acc[mi][ni][1]));
            *reinterpret_cast<__half2*>(p + (size_t)8 * Ncols) =
                make_half2(__float2half_rn(acc[mi][ni][2]),
                           __float2half_rn(acc[mi][ni][3]));
        }
    }
}

// ---------------------------------------------------------------------------
// Kernel 4: per-token epilogue — rmsnorm(q,k), gamma, RoPE, transpose, repeat
// Vectorized: 16B loads, warp-shuffle reduction, float4 stores.
// ---------------------------------------------------------------------------
__device__ __forceinline__ void unpack8(uint4 u, float* f) {
    __half2 h;
    h = *reinterpret_cast<__half2*>(&u.x); f[0] = __low2float(h); f[1] = __high2float(h);
    h = *reinterpret_cast<__half2*>(&u.y); f[2] = __low2float(h); f[3] = __high2float(h);
    h = *reinterpret_cast<__half2*>(&u.z); f[4] = __low2float(h); f[5] = __high2float(h);
    h = *reinterpret_cast<__half2*>(&u.w); f[6] = __low2float(h); f[7] = __high2float(h);
}

__global__ __launch_bounds__(256) void epilogue_kernel(
    const float* __restrict__ gq,
    const float* __restrict__ gk,
    float* __restrict__ out)
{
    const int bt = blockIdx.x;
    const int b = bt >> 12;
    const int t = bt & 4095;
    const __half* row = g_Ch + (size_t)bt * Ncols;
    const int tid = threadIdx.x;
    const int lane = tid & 31;
    const int wid = tid >> 5;

    // ---- loads (vectorized) ----
    float qf[16], kf[4], vf[4];
    {
        const uint4* qp = reinterpret_cast<const uint4*>(row + tid * 16);
        unpack8(qp[0], qf);
        unpack8(qp[1], qf + 8);
        uint2 ku = *reinterpret_cast<const uint2*>(row + 4096 + tid * 4);
        __half2 h;
        h = *reinterpret_cast<__half2*>(&ku.x); kf[0] = __low2float(h); kf[1] = __high2float(h);
        h = *reinterpret_cast<__half2*>(&ku.y); kf[2] = __low2float(h); kf[3] = __high2float(h);
        uint2 vu = *reinterpret_cast<const uint2*>(row + 5120 + tid * 4);
        h = *reinterpret_cast<__half2*>(&vu.x); vf[0] = __low2float(h); vf[1] = __high2float(h);
        h = *reinterpret_cast<__half2*>(&vu.y); vf[2] = __low2float(h); vf[3] = __high2float(h);
    }

    // ---- sums of squares ----
    float ssq_q = 0.0f, ssq_k = 0.0f;
    #pragma unroll
    for (int i = 0; i < 16; i++) ssq_q += qf[i] * qf[i];
    #pragma unroll
    for (int i = 0; i < 4; i++) ssq_k += kf[i] * kf[i];

    // warp shuffle reduce, then 8-way smem combine
    #pragma unroll
    for (int o = 16; o > 0; o >>= 1) {
        ssq_q += __shfl_xor_sync(0xFFFFFFFFu, ssq_q, o);
        ssq_k += __shfl_xor_sync(0xFFFFFFFFu, ssq_k, o);
    }
    __shared__ float s_q[8], s_k[8];
    if (lane == 0) { s_q[wid] = ssq_q; s_k[wid] = ssq_k; }
    __syncthreads();
    float tq = 0.0f, tk = 0.0f;
    #pragma unroll
    for (int i = 0; i < 8; i++) { tq += s_q[i]; tk += s_k[i]; }
    const float rs_q = rsqrtf(tq * (1.0f / 4096.0f) + 1e-5f);
    const float rs_k = rsqrtf(tk * (1.0f / 1024.0f) + 1e-5f);

    const float2* tab = g_tab + t * 64;
    float* outq = out;
    float* outk = out + (size_t)33554432;   // B*H*T*DH
    float* outv = out + (size_t)67108864;

    // ---- Q: rmsnorm + gamma + rope -> [b, h, t, 2*j0 .. 2*j0+16) ----
    {
        const int h = tid >> 3;            // head (8 pairs per thread, 64 per head)
        const int j0 = (tid * 8) & 63;     // first pair index within head
        float gqv[16];
        const float4* gp = reinterpret_cast<const float4*>(gq + tid * 16);
        #pragma unroll
        for (int i = 0; i < 4; i++) {
            float4 g4 = gp[i];
            gqv[4 * i] = g4.x; gqv[4 * i + 1] = g4.y;
            gqv[4 * i + 2] = g4.z; gqv[4 * i + 3] = g4.w;
        }
        float r[16];
        #pragma unroll
        for (int i = 0; i < 8; i++) {
            float2 cs = tab[j0 + i];
            float x1 = qf[2 * i] * rs_q * gqv[2 * i];
            float x2 = qf[2 * i + 1] * rs_q * gqv[2 * i + 1];
            r[2 * i]     = x1 * cs.x - x2 * cs.y;
            r[2 * i + 1] = x1 * cs.y + x2 * cs.x;
        }
        float4* dst = reinterpret_cast<float4*>(
            outq + (((size_t)(b * Hh + h) * Tt + t) * DH + 2 * j0));
        #pragma unroll
        for (int i = 0; i < 4; i++)
            dst[i] = make_float4(r[4 * i], r[4 * i + 1], r[4 * i + 2], r[4 * i + 3]);
    }

    // ---- K: rmsnorm + gamma + rope, repeated 4x ----
    {
        const int kh = tid >> 5;           // kv head (2 pairs/thread, 64 per head)
        const int j0 = (tid * 2) & 63;
        float4 g4 = *reinterpret_cast<const float4*>(gk + tid * 4);
        float2 cs0 = tab[j0];
        float2 cs1 = tab[j0 + 1];
        float x1 = kf[0] * rs_k * g4.x;
        float x2 = kf[1] * rs_k * g4.y;
        float y1 = kf[2] * rs_k * g4.z;
        float y2 = kf[3] * rs_k * g4.w;
        float4 r = make_float4(x1 * cs0.x - x2 * cs0.y, x1 * cs0.y + x2 * cs0.x,
                               y1 * cs1.x - y2 * cs1.y, y1 * cs1.y + y2 * cs1.x);
        #pragma unroll
        for (int rr = 0; rr < 4; rr++) {
            int h = kh * 4 + rr;
            *reinterpret_cast<float4*>(
                outk + (((size_t)(b * Hh + h) * Tt + t) * DH + 2 * j0)) = r;
        }
    }

    // ---- V: plain, repeated 4x ----
    {
        const int kh = tid >> 5;
        const int d = (tid * 4) & 127;
        float4 r = make_float4(vf[0], vf[1], vf[2], vf[3]);
        #pragma unroll
        for (int rr = 0; rr < 4; rr++) {
            int h = kh * 4 + rr;
            *reinterpret_cast<float4*>(
                outv + (((size_t)(b * Hh + h) * Tt + t) * DH + d)) = r;
        }
    }
}

// ---------------------------------------------------------------------------
extern "C" void kernel_launch(void* const* d_in, const int* in_sizes, int n_in,
                              void* d_out, int out_size)
{
    const float* x  = (const float*)d_in[0];
    const float* Wq = (const float*)d_in[1];
    const float* Wk = (const float*)d_in[2];
    const float* Wv = (const float*)d_in[3];
    const float* gq = (const float*)d_in[4];
    const float* gk = (const float*)d_in[5];
    float* out = (float*)d_out;

    cudaFuncSetAttribute(gemm_kernel,
                         cudaFuncAttributeMaxDynamicSharedMemorySize, SMEM_BYTES);

    rope_table_kernel<<<(Tt * 64 + 255) / 256, 256>>>();
    convert_x_kernel<<<(int)(((size_t)Mrows * Kdim / 4 + 255) / 256), 256>>>(x);
    convert_w_kernel<<<dim3(Ncols / 32, Kdim / 32), dim3(32, 8)>>>(Wq, Wk, Wv);
    gemm_kernel<<<MT * NT, 256, SMEM_BYTES>>>();
    epilogue_kernel<<<Mrows, 256>>>(gq, gk, out);
}

// round 9
// speedup vs baseline: 1.1042x; 1.0135x over previous
#include <cuda_runtime.h>
#include <cuda_fp16.h>
#include <cstdint>

// Problem constants
#define Bb 2
#define Tt 4096
#define Dd 4096
#define Hh 32
#define HKV 8
#define DH 128
#define Mrows 8192         // B*T
#define Ncols 6144         // D + 2*HKV*DH
#define Kdim 4096

// GEMM tiling (fp16 legacy mma + ldmatrix), 256 thr = 8 warps (2Mx4N), warp 64x32
#define BM 128
#define BN 128
#define BK 64
#define NKITER (Kdim / BK)            // 64
#define STAGES 3
#define A_STAGE_BYTES (BM * BK * 2)   // 16384
#define B_STAGE_BYTES (BN * BK * 2)   // 16384
#define SMEM_BYTES (STAGES * (A_STAGE_BYTES + B_STAGE_BYTES))  // 98304

#define MT (Mrows / BM)   // 64
#define NT (Ncols / BN)   // 48
#define GM 16

// merged prep kernel block ranges
#define XBLOCKS 32768     // x convert: 8192*4096/4 float4 / 256 thr
#define WBLOCKS 24576     // W convert: 192 * 128 tiles of 32x32
#define RBLOCKS 1024      // rope table: 4096*64 / 256

// Scratch device globals
__device__ __half g_Ch[(size_t)Mrows * Ncols];        // GEMM result fp16 (~100 MB)
__device__ __half g_xh[(size_t)Mrows * Kdim];         // fp16 x, [M,K] row-major
__device__ __half g_Wth[(size_t)Ncols * Kdim];        // fp16 W^T, [N,K] row-major
__device__ float2 g_tab[Tt * (DH / 2)];               // RoPE (cos,sin) table

// ---------------------------------------------------------------------------
// PTX helpers
// ---------------------------------------------------------------------------
__device__ __forceinline__ void cp_async16(uint32_t dst, const void* src) {
    asm volatile("cp.async.cg.shared.global [%0], [%1], 16;\n" :: "r"(dst), "l"(src));
}
__device__ __forceinline__ void cp_commit() {
    asm volatile("cp.async.commit_group;\n" ::: "memory");
}
__device__ __forceinline__ void cp_wait1() {
    asm volatile("cp.async.wait_group 1;\n" ::: "memory");
}
__device__ __forceinline__ void ldmatrix_x4(uint32_t r[4], uint32_t addr) {
    asm volatile("ldmatrix.sync.aligned.m8n8.x4.shared.b16 {%0,%1,%2,%3}, [%4];"
                 : "=r"(r[0]), "=r"(r[1]), "=r"(r[2]), "=r"(r[3]) : "r"(addr));
}
__device__ __forceinline__ void mma_f16(float c[4], const uint32_t a[4], const uint32_t b[2]) {
    asm volatile(
        "mma.sync.aligned.m16n8k16.row.col.f32.f16.f16.f32 "
        "{%0,%1,%2,%3}, {%4,%5,%6,%7}, {%8,%9}, {%0,%1,%2,%3};"
        : "+f"(c[0]), "+f"(c[1]), "+f"(c[2]), "+f"(c[3])
        : "r"(a[0]), "r"(a[1]), "r"(a[2]), "r"(a[3]), "r"(b[0]), "r"(b[1]));
}
__device__ __forceinline__ uint32_t swz128(uint32_t off) {
    return off ^ ((off >> 3) & 0x70);
}

// ---------------------------------------------------------------------------
// Kernel 1: merged prep — x->fp16, W->fp16 transposed, RoPE table
// 58368 blocks x 256 threads, branch on blockIdx.x (uniform per block)
// ---------------------------------------------------------------------------
__global__ __launch_bounds__(256) void prep_kernel(
    const float* __restrict__ x,
    const float* __restrict__ Wq,
    const float* __restrict__ Wk,
    const float* __restrict__ Wv)
{
    __shared__ __half tile[32][34];
    const int bid = blockIdx.x;
    const int tid = threadIdx.x;

    if (bid < XBLOCKS) {
        // ---- convert x -> fp16 ----
        size_t i = (size_t)bid * 256 + tid;       // float4 index
        float4 v = reinterpret_cast<const float4*>(x)[i];
        __half2 h0 = make_half2(__float2half_rn(v.x), __float2half_rn(v.y));
        __half2 h1 = make_half2(__float2half_rn(v.z), __float2half_rn(v.w));
        reinterpret_cast<__half2*>(g_xh)[2 * i]     = h0;
        reinterpret_cast<__half2*>(g_xh)[2 * i + 1] = h1;
    } else if (bid < XBLOCKS + WBLOCKS) {
        // ---- transpose + convert [Wq|Wk|Wv] -> fp16 g_Wth[n][k] ----
        const int w = bid - XBLOCKS;
        const int n0 = (w % 192) * 32;
        const int k0 = (w / 192) * 32;
        const int tx = tid & 31;
        const int ty = tid >> 5;
        #pragma unroll
        for (int i = 0; i < 4; i++) {
            int k = k0 + ty + i * 8;
            int n = n0 + tx;
            float v;
            if (n < 4096)       v = Wq[(size_t)k * 4096 + n];
            else if (n < 5120)  v = Wk[(size_t)k * 1024 + (n - 4096)];
            else                v = Wv[(size_t)k * 1024 + (n - 5120)];
            tile[ty + i * 8][tx] = __float2half_rn(v);
        }
        __syncthreads();
        #pragma unroll
        for (int i = 0; i < 4; i++) {
            int n = n0 + ty + i * 8;
            int k = k0 + tx;
            g_Wth[(size_t)n * Kdim + k] = tile[tx][ty + i * 8];
        }
    } else {
        // ---- RoPE cos/sin table ----
        int idx = (bid - XBLOCKS - WBLOCKS) * 256 + tid;
        int t = idx >> 6;
        int j = idx & 63;
        double inv = exp2(-((double)(2 * j)) * (1.0 / 128.0) * 13.287712379549449);
        double a = (double)t * inv;
        double red = remainder(a, 6.283185307179586477);
        float s, c;
        sincosf((float)red, &s, &c);
        g_tab[idx] = make_float2(c, s);
    }
}

// ---------------------------------------------------------------------------
// Kernel 2: fp16 GEMM  C = g_xh @ g_Wth^T   (ldmatrix + HMMA)  [R4 loop order]
// 3072 CTAs (64 M x 48 N, GROUP_M=16), 256 thr = 8 warps (2M x 4N), warp 64x32
// ---------------------------------------------------------------------------
__global__ __launch_bounds__(256, 2) void gemm_kernel() {
    extern __shared__ char smem[];
    const uint32_t smem_base = (uint32_t)__cvta_generic_to_shared(smem);
    const uint32_t a_base = smem_base;                          // 3 x 16KB
    const uint32_t b_base = smem_base + STAGES * A_STAGE_BYTES; // 3 x 16KB

    int gid = blockIdx.x;
    int group = gid / (GM * NT);
    int rem = gid % (GM * NT);
    const int mt = group * GM + (rem % GM);
    const int nt = rem / GM;
    const int m0 = mt * BM;
    const int n0 = nt * BN;

    const int tid = threadIdx.x;
    const int lane = tid & 31;
    const int wid = tid >> 5;
    const int warp_m = wid & 1;   // 0..1, 64 rows
    const int warp_n = wid >> 1;  // 0..3, 32 cols

    float acc[4][4][4];
    #pragma unroll
    for (int i = 0; i < 4; i++)
        #pragma unroll
        for (int j = 0; j < 4; j++)
            #pragma unroll
            for (int r = 0; r < 4; r++)
                acc[i][j][r] = 0.0f;

    auto issue = [&](int ktile, int slot) {
        const int k0 = ktile * BK;
        const uint32_t a_dst = a_base + slot * A_STAGE_BYTES;
        const uint32_t b_dst = b_base + slot * B_STAGE_BYTES;
        const __half* a_src = g_xh + (size_t)m0 * Kdim + k0;
        const __half* b_src = g_Wth + (size_t)n0 * Kdim + k0;
        #pragma unroll
        for (int i = 0; i < 4; i++) {
            int idx = tid + i * 256;       // 0..1023
            int row = idx >> 3;            // 0..127
            int kq = idx & 7;              // 16B chunk within 128B row
            cp_async16(a_dst + swz128(row * 128 + kq * 16),
                       a_src + (size_t)row * Kdim + kq * 8);
        }
        #pragma unroll
        for (int i = 0; i < 4; i++) {
            int idx = tid + i * 256;
            int row = idx >> 3;
            int kq = idx & 7;
            cp_async16(b_dst + swz128(row * 128 + kq * 16),
                       b_src + (size_t)row * Kdim + kq * 8);
        }
        cp_commit();
    };

    issue(0, 0);
    issue(1, 1);

    // ldmatrix lane addressing
    const int a_row = warp_m * 64 + (lane & 15);                      // + mi*16
    const int a_ch  = lane >> 4;                                      // + ks*2
    const int b_row = warp_n * 32 + (lane & 7) + ((lane >> 4) << 3);  // + ng*16
    const int b_ch  = (lane >> 3) & 1;                                // + ks*2

    #pragma unroll 1
    for (int it = 0; it < NKITER; it++) {
        const int slot = it % STAGES;
        cp_wait1();
        __syncthreads();

        {
            int lt = it + 2;
            if (lt < NKITER) issue(lt, lt % STAGES);
            else             cp_commit();     // empty group keeps wait accounting
        }

        const uint32_t A_s = a_base + slot * A_STAGE_BYTES;
        const uint32_t B_s = b_base + slot * B_STAGE_BYTES;

        #pragma unroll
        for (int ks = 0; ks < 4; ks++) {
            uint32_t a[4][4], b[2][4];
            #pragma unroll
            for (int mi = 0; mi < 4; mi++)
                ldmatrix_x4(a[mi], A_s + swz128((a_row + mi * 16) * 128 +
                                                (ks * 2 + a_ch) * 16));
            #pragma unroll
            for (int ng = 0; ng < 2; ng++)
                ldmatrix_x4(b[ng], B_s + swz128((b_row + ng * 16) * 128 +
                                                (ks * 2 + b_ch) * 16));
            #pragma unroll
            for (int mi = 0; mi < 4; mi++) {
                #pragma unroll
                for (int ng = 0; ng < 2; ng++) {
                    mma_f16(acc[mi][ng * 2],     a[mi], &b[ng][0]);
                    mma_f16(acc[mi][ng * 2 + 1], a[mi], &b[ng][2]);
                }
            }
        }
    }

    // write accumulators to fp16 scratch C
    const int nbase = n0 + warp_n * 32;
    #pragma unroll
    for (int mi = 0; mi < 4; mi++) {
        int row = m0 + warp_m * 64 + mi * 16 + (lane >> 2);
        #pragma unroll
        for (int ni = 0; ni < 4; ni++) {
            int col = nbase + ni * 8 + (lane & 3) * 2;
            __half* p = g_Ch + (size_t)row * Ncols + col;
            *reinterpret_cast<__half2*>(p) =
                make_half2(__float2half_rn(acc[mi][ni][0]),
                           __float2half_rn(acc[mi][ni][1]));
            *reinterpret_cast<__half2*>(p + (size_t)8 * Ncols) =
                make_half2(__float2half_rn(acc[mi][ni][2]),
                           __float2half_rn(acc[mi][ni][3]));
        }
    }
}

// ---------------------------------------------------------------------------
// Kernel 3: per-token epilogue — rmsnorm(q,k), gamma, RoPE, transpose, repeat
// Vectorized: 16B loads, warp-shuffle reduction, float4 stores.
// ---------------------------------------------------------------------------
__device__ __forceinline__ void unpack8(uint4 u, float* f) {
    __half2 h;
    h = *reinterpret_cast<__half2*>(&u.x); f[0] = __low2float(h); f[1] = __high2float(h);
    h = *reinterpret_cast<__half2*>(&u.y); f[2] = __low2float(h); f[3] = __high2float(h);
    h = *reinterpret_cast<__half2*>(&u.z); f[4] = __low2float(h); f[5] = __high2float(h);
    h = *reinterpret_cast<__half2*>(&u.w); f[6] = __low2float(h); f[7] = __high2float(h);
}

__global__ __launch_bounds__(256) void epilogue_kernel(
    const float* __restrict__ gq,
    const float* __restrict__ gk,
    float* __restrict__ out)
{
    const int bt = blockIdx.x;
    const int b = bt >> 12;
    const int t = bt & 4095;
    const __half* row = g_Ch + (size_t)bt * Ncols;
    const int tid = threadIdx.x;
    const int lane = tid & 31;
    const int wid = tid >> 5;

    // ---- loads (vectorized) ----
    float qf[16], kf[4], vf[4];
    {
        const uint4* qp = reinterpret_cast<const uint4*>(row + tid * 16);
        unpack8(qp[0], qf);
        unpack8(qp[1], qf + 8);
        uint2 ku = *reinterpret_cast<const uint2*>(row + 4096 + tid * 4);
        __half2 h;
        h = *reinterpret_cast<__half2*>(&ku.x); kf[0] = __low2float(h); kf[1] = __high2float(h);
        h = *reinterpret_cast<__half2*>(&ku.y); kf[2] = __low2float(h); kf[3] = __high2float(h);
        uint2 vu = *reinterpret_cast<const uint2*>(row + 5120 + tid * 4);
        h = *reinterpret_cast<__half2*>(&vu.x); vf[0] = __low2float(h); vf[1] = __high2float(h);
        h = *reinterpret_cast<__half2*>(&vu.y); vf[2] = __low2float(h); vf[3] = __high2float(h);
    }

    // ---- sums of squares ----
    float ssq_q = 0.0f, ssq_k = 0.0f;
    #pragma unroll
    for (int i = 0; i < 16; i++) ssq_q += qf[i] * qf[i];
    #pragma unroll
    for (int i = 0; i < 4; i++) ssq_k += kf[i] * kf[i];

    #pragma unroll
    for (int o = 16; o > 0; o >>= 1) {
        ssq_q += __shfl_xor_sync(0xFFFFFFFFu, ssq_q, o);
        ssq_k += __shfl_xor_sync(0xFFFFFFFFu, ssq_k, o);
    }
    __shared__ float s_q[8], s_k[8];
    if (lane == 0) { s_q[wid] = ssq_q; s_k[wid] = ssq_k; }
    __syncthreads();
    float tq = 0.0f, tk = 0.0f;
    #pragma unroll
    for (int i = 0; i < 8; i++) { tq += s_q[i]; tk += s_k[i]; }
    const float rs_q = rsqrtf(tq * (1.0f / 4096.0f) + 1e-5f);
    const float rs_k = rsqrtf(tk * (1.0f / 1024.0f) + 1e-5f);

    const float2* tab = g_tab + t * 64;
    float* outq = out;
    float* outk = out + (size_t)33554432;   // B*H*T*DH
    float* outv = out + (size_t)67108864;

    // ---- Q ----
    {
        const int h = tid >> 3;
        const int j0 = (tid * 8) & 63;
        float gqv[16];
        const float4* gp = reinterpret_cast<const float4*>(gq + tid * 16);
        #pragma unroll
        for (int i = 0; i < 4; i++) {
            float4 g4 = gp[i];
            gqv[4 * i] = g4.x; gqv[4 * i + 1] = g4.y;
            gqv[4 * i + 2] = g4.z; gqv[4 * i + 3] = g4.w;
        }
        float r[16];
        #pragma unroll
        for (int i = 0; i < 8; i++) {
            float2 cs = tab[j0 + i];
            float x1 = qf[2 * i] * rs_q * gqv[2 * i];
            float x2 = qf[2 * i + 1] * rs_q * gqv[2 * i + 1];
            r[2 * i]     = x1 * cs.x - x2 * cs.y;
            r[2 * i + 1] = x1 * cs.y + x2 * cs.x;
        }
        float4* dst = reinterpret_cast<float4*>(
            outq + (((size_t)(b * Hh + h) * Tt + t) * DH + 2 * j0));
        #pragma unroll
        for (int i = 0; i < 4; i++)
            dst[i] = make_float4(r[4 * i], r[4 * i + 1], r[4 * i + 2], r[4 * i + 3]);
    }

    // ---- K (repeated 4x) ----
    {
        const int kh = tid >> 5;
        const int j0 = (tid * 2) & 63;
        float4 g4 = *reinterpret_cast<const float4*>(gk + tid * 4);
        float2 cs0 = tab[j0];
        float2 cs1 = tab[j0 + 1];
        float x1 = kf[0] * rs_k * g4.x;
        float x2 = kf[1] * rs_k * g4.y;
        float y1 = kf[2] * rs_k * g4.z;
        float y2 = kf[3] * rs_k * g4.w;
        float4 r = make_float4(x1 * cs0.x - x2 * cs0.y, x1 * cs0.y + x2 * cs0.x,
                               y1 * cs1.x - y2 * cs1.y, y1 * cs1.y + y2 * cs1.x);
        #pragma unroll
        for (int rr = 0; rr < 4; rr++) {
            int h = kh * 4 + rr;
            *reinterpret_cast<float4*>(
                outk + (((size_t)(b * Hh + h) * Tt + t) * DH + 2 * j0)) = r;
        }
    }

    // ---- V (repeated 4x) ----
    {
        const int kh = tid >> 5;
        const int d = (tid * 4) & 127;
        float4 r = make_float4(vf[0], vf[1], vf[2], vf[3]);
        #pragma unroll
        for (int rr = 0; rr < 4; rr++) {
            int h = kh * 4 + rr;
            *reinterpret_cast<float4*>(
                outv + (((size_t)(b * Hh + h) * Tt + t) * DH + d)) = r;
        }
    }
}

// ---------------------------------------------------------------------------
extern "C" void kernel_launch(void* const* d_in, const int* in_sizes, int n_in,
                              void* d_out, int out_size)
{
    const float* x  = (const float*)d_in[0];
    const float* Wq = (const float*)d_in[1];
    const float* Wk = (const float*)d_in[2];
    const float* Wv = (const float*)d_in[3];
    const float* gq = (const float*)d_in[4];
    const float* gk = (const float*)d_in[5];
    float* out = (float*)d_out;

    cudaFuncSetAttribute(gemm_kernel,
                         cudaFuncAttributeMaxDynamicSharedMemorySize, SMEM_BYTES);

    prep_kernel<<<XBLOCKS + WBLOCKS + RBLOCKS, 256>>>(x, Wq, Wk, Wv);
    gemm_kernel<<<MT * NT, 256, SMEM_BYTES>>>();
    epilogue_kernel<<<Mrows, 256>>>(gq, gk, out);
}

// round 10
// speedup vs baseline: 1.1132x; 1.0081x over previous
#include <cuda_runtime.h>
#include <cuda_fp16.h>
#include <cstdint>

// Problem constants
#define Bb 2
#define Tt 4096
#define Dd 4096
#define Hh 32
#define HKV 8
#define DH 128
#define Mrows 8192         // B*T
#define Ncols 6144         // D + 2*HKV*DH
#define Kdim 4096

// GEMM tiling (fp16 legacy mma + ldmatrix), 256 thr = 8 warps (2Mx4N), warp 64x32
#define BM 128
#define BN 128
#define BK 64
#define NKITER (Kdim / BK)            // 64
#define STAGES 3
#define A_STAGE_BYTES (BM * BK * 2)   // 16384
#define B_STAGE_BYTES (BN * BK * 2)   // 16384
#define SMEM_BYTES (STAGES * (A_STAGE_BYTES + B_STAGE_BYTES))  // 98304

#define MT (Mrows / BM)   // 64
#define NT (Ncols / BN)   // 48
#define GM 16

// merged prep kernel block ranges
#define XBLOCKS 16384     // x convert: 33.5M halves / (256 thr * 8 halves)
#define WBLOCKS 12288     // W transpose: (4096/64) * (6144/32) tiles
#define RBLOCKS 1024      // rope table: 4096*64 / 256

// Scratch device globals
__device__ __half g_Ch[(size_t)Mrows * Ncols];        // GEMM result fp16 (~100 MB)
__device__ __half g_xh[(size_t)Mrows * Kdim];         // fp16 x, [M,K] row-major
__device__ __half g_Wth[(size_t)Ncols * Kdim];        // fp16 W^T, [N,K] row-major
__device__ float2 g_tab[Tt * (DH / 2)];               // RoPE (cos,sin) table

// ---------------------------------------------------------------------------
// PTX helpers
// ---------------------------------------------------------------------------
__device__ __forceinline__ void cp_async16(uint32_t dst, const void* src) {
    asm volatile("cp.async.cg.shared.global [%0], [%1], 16;\n" :: "r"(dst), "l"(src));
}
__device__ __forceinline__ void cp_commit() {
    asm volatile("cp.async.commit_group;\n" ::: "memory");
}
__device__ __forceinline__ void cp_wait1() {
    asm volatile("cp.async.wait_group 1;\n" ::: "memory");
}
__device__ __forceinline__ void ldmatrix_x4(uint32_t r[4], uint32_t addr) {
    asm volatile("ldmatrix.sync.aligned.m8n8.x4.shared.b16 {%0,%1,%2,%3}, [%4];"
                 : "=r"(r[0]), "=r"(r[1]), "=r"(r[2]), "=r"(r[3]) : "r"(addr));
}
__device__ __forceinline__ void mma_f16(float c[4], const uint32_t a[4], const uint32_t b[2]) {
    asm volatile(
        "mma.sync.aligned.m16n8k16.row.col.f32.f16.f16.f32 "
        "{%0,%1,%2,%3}, {%4,%5,%6,%7}, {%8,%9}, {%0,%1,%2,%3};"
        : "+f"(c[0]), "+f"(c[1]), "+f"(c[2]), "+f"(c[3])
        : "r"(a[0]), "r"(a[1]), "r"(a[2]), "r"(a[3]), "r"(b[0]), "r"(b[1]));
}
__device__ __forceinline__ uint32_t swz128(uint32_t off) {
    return off ^ ((off >> 3) & 0x70);
}

// ---------------------------------------------------------------------------
// Kernel 1: merged prep — x->fp16 (16B stores), W->fp16 transposed (16B stores),
// RoPE table. 29696 blocks x 256 threads, branch on blockIdx.x.
// ---------------------------------------------------------------------------
__global__ __launch_bounds__(256) void prep_kernel(
    const float* __restrict__ x,
    const float* __restrict__ Wq,
    const float* __restrict__ Wk,
    const float* __restrict__ Wv)
{
    __shared__ __half tile[64][33];
    const int bid = blockIdx.x;
    const int tid = threadIdx.x;

    if (bid < XBLOCKS) {
        // ---- convert x -> fp16: 8 halves per thread, one 16B store ----
        size_t i = (size_t)bid * 256 + tid;               // uint4 (8-half) index
        const float4* xp = reinterpret_cast<const float4*>(x) + 2 * i;
        float4 v0 = xp[0];
        float4 v1 = xp[1];
        uint4 o;
        __half2 h;
        h = make_half2(__float2half_rn(v0.x), __float2half_rn(v0.y)); o.x = *reinterpret_cast<uint32_t*>(&h);
        h = make_half2(__float2half_rn(v0.z), __float2half_rn(v0.w)); o.y = *reinterpret_cast<uint32_t*>(&h);
        h = make_half2(__float2half_rn(v1.x), __float2half_rn(v1.y)); o.z = *reinterpret_cast<uint32_t*>(&h);
        h = make_half2(__float2half_rn(v1.z), __float2half_rn(v1.w)); o.w = *reinterpret_cast<uint32_t*>(&h);
        reinterpret_cast<uint4*>(g_xh)[i] = o;
    } else if (bid < XBLOCKS + WBLOCKS) {
        // ---- transpose + convert [Wq|Wk|Wv] -> fp16 g_Wth[n][k] ----
        // tile: 64 k-rows x 32 n-cols
        const int w = bid - XBLOCKS;
        const int n0 = (w % 192) * 32;
        const int k0 = (w / 192) * 64;
        const int tx = tid & 31;      // n within tile
        const int ty = tid >> 5;      // k row group (8 rows, 8 iters)
        #pragma unroll
        for (int i = 0; i < 8; i++) {
            int k = k0 + ty + i * 8;
            int n = n0 + tx;
            float v;
            if (n < 4096)       v = Wq[(size_t)k * 4096 + n];
            else if (n < 5120)  v = Wk[(size_t)k * 1024 + (n - 4096)];
            else                v = Wv[(size_t)k * 1024 + (n - 5120)];
            tile[ty + i * 8][tx] = __float2half_rn(v);
        }
        __syncthreads();
        // write: row r (n), 8 threads x 8 halves cover 64 k = 128B
        const int r = tid >> 3;       // 0..31 (n within tile)
        const int c = tid & 7;        // 0..7  (8-half chunk within k)
        __half h8[8];
        #pragma unroll
        for (int j = 0; j < 8; j++)
            h8[j] = tile[c * 8 + j][r];
        *reinterpret_cast<uint4*>(g_Wth + (size_t)(n0 + r) * Kdim + k0 + c * 8) =
            *reinterpret_cast<uint4*>(h8);
    } else {
        // ---- RoPE cos/sin table ----
        int idx = (bid - XBLOCKS - WBLOCKS) * 256 + tid;
        int t = idx >> 6;
        int j = idx & 63;
        double inv = exp2(-((double)(2 * j)) * (1.0 / 128.0) * 13.287712379549449);
        double a = (double)t * inv;
        double red = remainder(a, 6.283185307179586477);
        float s, c;
        sincosf((float)red, &s, &c);
        g_tab[idx] = make_float2(c, s);
    }
}

// ---------------------------------------------------------------------------
// Kernel 2: fp16 GEMM  C = g_xh @ g_Wth^T   (ldmatrix + HMMA)  [R4 loop order]
// 3072 CTAs (64 M x 48 N, GROUP_M=16), 256 thr = 8 warps (2M x 4N), warp 64x32
// ---------------------------------------------------------------------------
__global__ __launch_bounds__(256, 2) void gemm_kernel() {
    extern __shared__ char smem[];
    const uint32_t smem_base = (uint32_t)__cvta_generic_to_shared(smem);
    const uint32_t a_base = smem_base;                          // 3 x 16KB
    const uint32_t b_base = smem_base + STAGES * A_STAGE_BYTES; // 3 x 16KB

    int gid = blockIdx.x;
    int group = gid / (GM * NT);
    int rem = gid % (GM * NT);
    const int mt = group * GM + (rem % GM);
    const int nt = rem / GM;
    const int m0 = mt * BM;
    const int n0 = nt * BN;

    const int tid = threadIdx.x;
    const int lane = tid & 31;
    const int wid = tid >> 5;
    const int warp_m = wid & 1;   // 0..1, 64 rows
    const int warp_n = wid >> 1;  // 0..3, 32 cols

    float acc[4][4][4];
    #pragma unroll
    for (int i = 0; i < 4; i++)
        #pragma unroll
        for (int j = 0; j < 4; j++)
            #pragma unroll
            for (int r = 0; r < 4; r++)
                acc[i][j][r] = 0.0f;

    auto issue = [&](int ktile, int slot) {
        const int k0 = ktile * BK;
        const uint32_t a_dst = a_base + slot * A_STAGE_BYTES;
        const uint32_t b_dst = b_base + slot * B_STAGE_BYTES;
        const __half* a_src = g_xh + (size_t)m0 * Kdim + k0;
        const __half* b_src = g_Wth + (size_t)n0 * Kdim + k0;
        #pragma unroll
        for (int i = 0; i < 4; i++) {
            int idx = tid + i * 256;       // 0..1023
            int row = idx >> 3;            // 0..127
            int kq = idx & 7;              // 16B chunk within 128B row
            cp_async16(a_dst + swz128(row * 128 + kq * 16),
                       a_src + (size_t)row * Kdim + kq * 8);
        }
        #pragma unroll
        for (int i = 0; i < 4; i++) {
            int idx = tid + i * 256;
            int row = idx >> 3;
            int kq = idx & 7;
            cp_async16(b_dst + swz128(row * 128 + kq * 16),
                       b_src + (size_t)row * Kdim + kq * 8);
        }
        cp_commit();
    };

    issue(0, 0);
    issue(1, 1);

    // ldmatrix lane addressing
    const int a_row = warp_m * 64 + (lane & 15);                      // + mi*16
    const int a_ch  = lane >> 4;                                      // + ks*2
    const int b_row = warp_n * 32 + (lane & 7) + ((lane >> 4) << 3);  // + ng*16
    const int b_ch  = (lane >> 3) & 1;                                // + ks*2

    #pragma unroll 1
    for (int it = 0; it < NKITER; it++) {
        const int slot = it % STAGES;
        cp_wait1();
        __syncthreads();

        {
            int lt = it + 2;
            if (lt < NKITER) issue(lt, lt % STAGES);
            else             cp_commit();     // empty group keeps wait accounting
        }

        const uint32_t A_s = a_base + slot * A_STAGE_BYTES;
        const uint32_t B_s = b_base + slot * B_STAGE_BYTES;

        #pragma unroll
        for (int ks = 0; ks < 4; ks++) {
            uint32_t a[4][4], b[2][4];
            #pragma unroll
            for (int mi = 0; mi < 4; mi++)
                ldmatrix_x4(a[mi], A_s + swz128((a_row + mi * 16) * 128 +
                                                (ks * 2 + a_ch) * 16));
            #pragma unroll
            for (int ng = 0; ng < 2; ng++)
                ldmatrix_x4(b[ng], B_s + swz128((b_row + ng * 16) * 128 +
                                                (ks * 2 + b_ch) * 16));
            #pragma unroll
            for (int mi = 0; mi < 4; mi++) {
                #pragma unroll
                for (int ng = 0; ng < 2; ng++) {
                    mma_f16(acc[mi][ng * 2],     a[mi], &b[ng][0]);
                    mma_f16(acc[mi][ng * 2 + 1], a[mi], &b[ng][2]);
                }
            }
        }
    }

    // write accumulators to fp16 scratch C
    const int nbase = n0 + warp_n * 32;
    #pragma unroll
    for (int mi = 0; mi < 4; mi++) {
        int row = m0 + warp_m * 64 + mi * 16 + (lane >> 2);
        #pragma unroll
        for (int ni = 0; ni < 4; ni++) {
            int col = nbase + ni * 8 + (lane & 3) * 2;
            __half* p = g_Ch + (size_t)row * Ncols + col;
            *reinterpret_cast<__half2*>(p) =
                make_half2(__float2half_rn(acc[mi][ni][0]),
                           __float2half_rn(acc[mi][ni][1]));
            *reinterpret_cast<__half2*>(p + (size_t)8 * Ncols) =
                make_half2(__float2half_rn(acc[mi][ni][2]),
                           __float2half_rn(acc[mi][ni][3]));
        }
    }
}

// ---------------------------------------------------------------------------
// Kernel 3: per-token epilogue — rmsnorm(q,k), gamma, RoPE, transpose, repeat
// Vectorized: 16B loads, warp-shuffle reduction, float4 stores.
// ---------------------------------------------------------------------------
__device__ __forceinline__ void unpack8(uint4 u, float* f) {
    __half2 h;
    h = *reinterpret_cast<__half2*>(&u.x); f[0] = __low2float(h); f[1] = __high2float(h);
    h = *reinterpret_cast<__half2*>(&u.y); f[2] = __low2float(h); f[3] = __high2float(h);
    h = *reinterpret_cast<__half2*>(&u.z); f[4] = __low2float(h); f[5] = __high2float(h);
    h = *reinterpret_cast<__half2*>(&u.w); f[6] = __low2float(h); f[7] = __high2float(h);
}

__global__ __launch_bounds__(256) void epilogue_kernel(
    const float* __restrict__ gq,
    const float* __restrict__ gk,
    float* __restrict__ out)
{
    const int bt = blockIdx.x;
    const int b = bt >> 12;
    const int t = bt & 4095;
    const __half* row = g_Ch + (size_t)bt * Ncols;
    const int tid = threadIdx.x;
    const int lane = tid & 31;
    const int wid = tid >> 5;

    // ---- loads (vectorized) ----
    float qf[16], kf[4], vf[4];
    {
        const uint4* qp = reinterpret_cast<const uint4*>(row + tid * 16);
        unpack8(qp[0], qf);
        unpack8(qp[1], qf + 8);
        uint2 ku = *reinterpret_cast<const uint2*>(row + 4096 + tid * 4);
        __half2 h;
        h = *reinterpret_cast<__half2*>(&ku.x); kf[0] = __low2float(h); kf[1] = __high2float(h);
        h = *reinterpret_cast<__half2*>(&ku.y); kf[2] = __low2float(h); kf[3] = __high2float(h);
        uint2 vu = *reinterpret_cast<const uint2*>(row + 5120 + tid * 4);
        h = *reinterpret_cast<__half2*>(&vu.x); vf[0] = __low2float(h); vf[1] = __high2float(h);
        h = *reinterpret_cast<__half2*>(&vu.y); vf[2] = __low2float(h); vf[3] = __high2float(h);
    }

    // ---- sums of squares ----
    float ssq_q = 0.0f, ssq_k = 0.0f;
    #pragma unroll
    for (int i = 0; i < 16; i++) ssq_q += qf[i] * qf[i];
    #pragma unroll
    for (int i = 0; i < 4; i++) ssq_k += kf[i] * kf[i];

    #pragma unroll
    for (int o = 16; o > 0; o >>= 1) {
        ssq_q += __shfl_xor_sync(0xFFFFFFFFu, ssq_q, o);
        ssq_k += __shfl_xor_sync(0xFFFFFFFFu, ssq_k, o);
    }
    __shared__ float s_q[8], s_k[8];
    if (lane == 0) { s_q[wid] = ssq_q; s_k[wid] = ssq_k; }
    __syncthreads();
    float tq = 0.0f, tk = 0.0f;
    #pragma unroll
    for (int i = 0; i < 8; i++) { tq += s_q[i]; tk += s_k[i]; }
    const float rs_q = rsqrtf(tq * (1.0f / 4096.0f) + 1e-5f);
    const float rs_k = rsqrtf(tk * (1.0f / 1024.0f) + 1e-5f);

    const float2* tab = g_tab + t * 64;
    float* outq = out;
    float* outk = out + (size_t)33554432;   // B*H*T*DH
    float* outv = out + (size_t)67108864;

    // ---- Q ----
    {
        const int h = tid >> 3;
        const int j0 = (tid * 8) & 63;
        float gqv[16];
        const float4* gp = reinterpret_cast<const float4*>(gq + tid * 16);
        #pragma unroll
        for (int i = 0; i < 4; i++) {
            float4 g4 = gp[i];
            gqv[4 * i] = g4.x; gqv[4 * i + 1] = g4.y;
            gqv[4 * i + 2] = g4.z; gqv[4 * i + 3] = g4.w;
        }
        float r[16];
        #pragma unroll
        for (int i = 0; i < 8; i++) {
            float2 cs = tab[j0 + i];
            float x1 = qf[2 * i] * rs_q * gqv[2 * i];
            float x2 = qf[2 * i + 1] * rs_q * gqv[2 * i + 1];
            r[2 * i]     = x1 * cs.x - x2 * cs.y;
            r[2 * i + 1] = x1 * cs.y + x2 * cs.x;
        }
        float4* dst = reinterpret_cast<float4*>(
            outq + (((size_t)(b * Hh + h) * Tt + t) * DH + 2 * j0));
        #pragma unroll
        for (int i = 0; i < 4; i++)
            dst[i] = make_float4(r[4 * i], r[4 * i + 1], r[4 * i + 2], r[4 * i + 3]);
    }

    // ---- K (repeated 4x) ----
    {
        const int kh = tid >> 5;
        const int j0 = (tid * 2) & 63;
        float4 g4 = *reinterpret_cast<const float4*>(gk + tid * 4);
        float2 cs0 = tab[j0];
        float2 cs1 = tab[j0 + 1];
        float x1 = kf[0] * rs_k * g4.x;
        float x2 = kf[1] * rs_k * g4.y;
        float y1 = kf[2] * rs_k * g4.z;
        float y2 = kf[3] * rs_k * g4.w;
        float4 r = make_float4(x1 * cs0.x - x2 * cs0.y, x1 * cs0.y + x2 * cs0.x,
                               y1 * cs1.x - y2 * cs1.y, y1 * cs1.y + y2 * cs1.x);
        #pragma unroll
        for (int rr = 0; rr < 4; rr++) {
            int h = kh * 4 + rr;
            *reinterpret_cast<float4*>(
                outk + (((size_t)(b * Hh + h) * Tt + t) * DH + 2 * j0)) = r;
        }
    }

    // ---- V (repeated 4x) ----
    {
        const int kh = tid >> 5;
        const int d = (tid * 4) & 127;
        float4 r = make_float4(vf[0], vf[1], vf[2], vf[3]);
        #pragma unroll
        for (int rr = 0; rr < 4; rr++) {
            int h = kh * 4 + rr;
            *reinterpret_cast<float4*>(
                outv + (((size_t)(b * Hh + h) * Tt + t) * DH + d)) = r;
        }
    }
}

// ---------------------------------------------------------------------------
extern "C" void kernel_launch(void* const* d_in, const int* in_sizes, int n_in,
                              void* d_out, int out_size)
{
    const float* x  = (const float*)d_in[0];
    const float* Wq = (const float*)d_in[1];
    const float* Wk = (const float*)d_in[2];
    const float* Wv = (const float*)d_in[3];
    const float* gq = (const float*)d_in[4];
    const float* gk = (const float*)d_in[5];
    float* out = (float*)d_out;

    cudaFuncSetAttribute(gemm_kernel,
                         cudaFuncAttributeMaxDynamicSharedMemorySize, SMEM_BYTES);

    prep_kernel<<<XBLOCKS + WBLOCKS + RBLOCKS, 256>>>(x, Wq, Wk, Wv);
    gemm_kernel<<<MT * NT, 256, SMEM_BYTES>>>();
    epilogue_kernel<<<Mrows, 256>>>(gq, gk, out);
}

// round 11
// speedup vs baseline: 1.1220x; 1.0079x over previous
#include <cuda_runtime.h>
#include <cuda_fp16.h>
#include <cstdint>

// Problem constants
#define Bb 2
#define Tt 4096
#define Dd 4096
#define Hh 32
#define HKV 8
#define DH 128
#define Mrows 8192         // B*T
#define Ncols 6144         // D + 2*HKV*DH
#define Kdim 4096

// GEMM tiling (fp16 legacy mma + ldmatrix), 256 thr = 8 warps (2Mx4N), warp 64x32
#define BM 128
#define BN 128
#define BK 64
#define NKITER (Kdim / BK)            // 64
#define STAGES 3
#define A_STAGE_BYTES (BM * BK * 2)   // 16384
#define B_STAGE_BYTES (BN * BK * 2)   // 16384
#define SMEM_BYTES (STAGES * (A_STAGE_BYTES + B_STAGE_BYTES))  // 98304

#define MT (Mrows / BM)   // 64
#define NT (Ncols / BN)   // 48
#define GM 16

// merged prep kernel block ranges — rope FIRST so its fp64 latency overlaps
// the memory-bound x/W sections instead of trailing them as an idle tail.
#define RBLOCKS 1024      // rope table: 4096*64 / 256
#define WBLOCKS 12288     // W transpose: (4096/64) * (6144/32) tiles
#define XBLOCKS 16384     // x convert: 33.5M halves / (256 thr * 8 halves)

// Scratch device globals
__device__ __half g_Ch[(size_t)Mrows * Ncols];        // GEMM result fp16 (~100 MB)
__device__ __half g_xh[(size_t)Mrows * Kdim];         // fp16 x, [M,K] row-major
__device__ __half g_Wth[(size_t)Ncols * Kdim];        // fp16 W^T, [N,K] row-major
__device__ float2 g_tab[Tt * (DH / 2)];               // RoPE (cos,sin) table

// ---------------------------------------------------------------------------
// PTX helpers
// ---------------------------------------------------------------------------
__device__ __forceinline__ void cp_async16(uint32_t dst, const void* src) {
    asm volatile("cp.async.cg.shared.global [%0], [%1], 16;\n" :: "r"(dst), "l"(src));
}
__device__ __forceinline__ void cp_commit() {
    asm volatile("cp.async.commit_group;\n" ::: "memory");
}
__device__ __forceinline__ void cp_wait1() {
    asm volatile("cp.async.wait_group 1;\n" ::: "memory");
}
__device__ __forceinline__ void ldmatrix_x4(uint32_t r[4], uint32_t addr) {
    asm volatile("ldmatrix.sync.aligned.m8n8.x4.shared.b16 {%0,%1,%2,%3}, [%4];"
                 : "=r"(r[0]), "=r"(r[1]), "=r"(r[2]), "=r"(r[3]) : "r"(addr));
}
__device__ __forceinline__ void mma_f16(float c[4], const uint32_t a[4], const uint32_t b[2]) {
    asm volatile(
        "mma.sync.aligned.m16n8k16.row.col.f32.f16.f16.f32 "
        "{%0,%1,%2,%3}, {%4,%5,%6,%7}, {%8,%9}, {%0,%1,%2,%3};"
        : "+f"(c[0]), "+f"(c[1]), "+f"(c[2]), "+f"(c[3])
        : "r"(a[0]), "r"(a[1]), "r"(a[2]), "r"(a[3]), "r"(b[0]), "r"(b[1]));
}
__device__ __forceinline__ uint32_t swz128(uint32_t off) {
    return off ^ ((off >> 3) & 0x70);
}

// ---------------------------------------------------------------------------
// Kernel 1: merged prep — RoPE table, W->fp16 transposed, x->fp16
// 29696 blocks x 256 threads, branch on blockIdx.x (rope scheduled first).
// ---------------------------------------------------------------------------
__global__ __launch_bounds__(256) void prep_kernel(
    const float* __restrict__ x,
    const float* __restrict__ Wq,
    const float* __restrict__ Wk,
    const float* __restrict__ Wv)
{
    __shared__ __half tile[64][33];
    const int bid = blockIdx.x;
    const int tid = threadIdx.x;

    if (bid < RBLOCKS) {
        // ---- RoPE cos/sin table ----
        int idx = bid * 256 + tid;
        int t = idx >> 6;
        int j = idx & 63;
        double inv = exp2(-((double)(2 * j)) * (1.0 / 128.0) * 13.287712379549449);
        double a = (double)t * inv;
        double red = remainder(a, 6.283185307179586477);
        float s, c;
        sincosf((float)red, &s, &c);
        g_tab[idx] = make_float2(c, s);
    } else if (bid < RBLOCKS + WBLOCKS) {
        // ---- transpose + convert [Wq|Wk|Wv] -> fp16 g_Wth[n][k] ----
        // tile: 64 k-rows x 32 n-cols
        const int w = bid - RBLOCKS;
        const int n0 = (w % 192) * 32;
        const int k0 = (w / 192) * 64;
        const int tx = tid & 31;      // n within tile
        const int ty = tid >> 5;      // k row group (8 rows, 8 iters)
        #pragma unroll
        for (int i = 0; i < 8; i++) {
            int k = k0 + ty + i * 8;
            int n = n0 + tx;
            float v;
            if (n < 4096)       v = Wq[(size_t)k * 4096 + n];
            else if (n < 5120)  v = Wk[(size_t)k * 1024 + (n - 4096)];
            else                v = Wv[(size_t)k * 1024 + (n - 5120)];
            tile[ty + i * 8][tx] = __float2half_rn(v);
        }
        __syncthreads();
        // write: row r (n), 8 threads x 8 halves cover 64 k = 128B
        const int r = tid >> 3;       // 0..31 (n within tile)
        const int c = tid & 7;        // 0..7  (8-half chunk within k)
        __half h8[8];
        #pragma unroll
        for (int j = 0; j < 8; j++)
            h8[j] = tile[c * 8 + j][r];
        *reinterpret_cast<uint4*>(g_Wth + (size_t)(n0 + r) * Kdim + k0 + c * 8) =
            *reinterpret_cast<uint4*>(h8);
    } else {
        // ---- convert x -> fp16: 8 halves per thread, one 16B store ----
        size_t i = (size_t)(bid - RBLOCKS - WBLOCKS) * 256 + tid;   // uint4 index
        const float4* xp = reinterpret_cast<const float4*>(x) + 2 * i;
        float4 v0 = xp[0];
        float4 v1 = xp[1];
        uint4 o;
        __half2 h;
        h = make_half2(__float2half_rn(v0.x), __float2half_rn(v0.y)); o.x = *reinterpret_cast<uint32_t*>(&h);
        h = make_half2(__float2half_rn(v0.z), __float2half_rn(v0.w)); o.y = *reinterpret_cast<uint32_t*>(&h);
        h = make_half2(__float2half_rn(v1.x), __float2half_rn(v1.y)); o.z = *reinterpret_cast<uint32_t*>(&h);
        h = make_half2(__float2half_rn(v1.z), __float2half_rn(v1.w)); o.w = *reinterpret_cast<uint32_t*>(&h);
        reinterpret_cast<uint4*>(g_xh)[i] = o;
    }
}

// ---------------------------------------------------------------------------
// Kernel 2: fp16 GEMM  C = g_xh @ g_Wth^T   (ldmatrix + HMMA)  [R4 loop order]
// 3072 CTAs (64 M x 48 N, GROUP_M=16), 256 thr = 8 warps (2M x 4N), warp 64x32
// ---------------------------------------------------------------------------
__global__ __launch_bounds__(256, 2) void gemm_kernel() {
    extern __shared__ char smem[];
    const uint32_t smem_base = (uint32_t)__cvta_generic_to_shared(smem);
    const uint32_t a_base = smem_base;                          // 3 x 16KB
    const uint32_t b_base = smem_base + STAGES * A_STAGE_BYTES; // 3 x 16KB

    int gid = blockIdx.x;
    int group = gid / (GM * NT);
    int rem = gid % (GM * NT);
    const int mt = group * GM + (rem % GM);
    const int nt = rem / GM;
    const int m0 = mt * BM;
    const int n0 = nt * BN;

    const int tid = threadIdx.x;
    const int lane = tid & 31;
    const int wid = tid >> 5;
    const int warp_m = wid & 1;   // 0..1, 64 rows
    const int warp_n = wid >> 1;  // 0..3, 32 cols

    float acc[4][4][4];
    #pragma unroll
    for (int i = 0; i < 4; i++)
        #pragma unroll
        for (int j = 0; j < 4; j++)
            #pragma unroll
            for (int r = 0; r < 4; r++)
                acc[i][j][r] = 0.0f;

    auto issue = [&](int ktile, int slot) {
        const int k0 = ktile * BK;
        const uint32_t a_dst = a_base + slot * A_STAGE_BYTES;
        const uint32_t b_dst = b_base + slot * B_STAGE_BYTES;
        const __half* a_src = g_xh + (size_t)m0 * Kdim + k0;
        const __half* b_src = g_Wth + (size_t)n0 * Kdim + k0;
        #pragma unroll
        for (int i = 0; i < 4; i++) {
            int idx = tid + i * 256;       // 0..1023
            int row = idx >> 3;            // 0..127
            int kq = idx & 7;              // 16B chunk within 128B row
            cp_async16(a_dst + swz128(row * 128 + kq * 16),
                       a_src + (size_t)row * Kdim + kq * 8);
        }
        #pragma unroll
        for (int i = 0; i < 4; i++) {
            int idx = tid + i * 256;
            int row = idx >> 3;
            int kq = idx & 7;
            cp_async16(b_dst + swz128(row * 128 + kq * 16),
                       b_src + (size_t)row * Kdim + kq * 8);
        }
        cp_commit();
    };

    issue(0, 0);
    issue(1, 1);

    // ldmatrix lane addressing
    const int a_row = warp_m * 64 + (lane & 15);                      // + mi*16
    const int a_ch  = lane >> 4;                                      // + ks*2
    const int b_row = warp_n * 32 + (lane & 7) + ((lane >> 4) << 3);  // + ng*16
    const int b_ch  = (lane >> 3) & 1;                                // + ks*2

    #pragma unroll 1
    for (int it = 0; it < NKITER; it++) {
        const int slot = it % STAGES;
        cp_wait1();
        __syncthreads();

        {
            int lt = it + 2;
            if (lt < NKITER) issue(lt, lt % STAGES);
            else             cp_commit();     // empty group keeps wait accounting
        }

        const uint32_t A_s = a_base + slot * A_STAGE_BYTES;
        const uint32_t B_s = b_base + slot * B_STAGE_BYTES;

        #pragma unroll
        for (int ks = 0; ks < 4; ks++) {
            uint32_t a[4][4], b[2][4];
            #pragma unroll
            for (int mi = 0; mi < 4; mi++)
                ldmatrix_x4(a[mi], A_s + swz128((a_row + mi * 16) * 128 +
                                                (ks * 2 + a_ch) * 16));
            #pragma unroll
            for (int ng = 0; ng < 2; ng++)
                ldmatrix_x4(b[ng], B_s + swz128((b_row + ng * 16) * 128 +
                                                (ks * 2 + b_ch) * 16));
            #pragma unroll
            for (int mi = 0; mi < 4; mi++) {
                #pragma unroll
                for (int ng = 0; ng < 2; ng++) {
                    mma_f16(acc[mi][ng * 2],     a[mi], &b[ng][0]);
                    mma_f16(acc[mi][ng * 2 + 1], a[mi], &b[ng][2]);
                }
            }
        }
    }

    // write accumulators to fp16 scratch C
    const int nbase = n0 + warp_n * 32;
    #pragma unroll
    for (int mi = 0; mi < 4; mi++) {
        int row = m0 + warp_m * 64 + mi * 16 + (lane >> 2);
        #pragma unroll
        for (int ni = 0; ni < 4; ni++) {
            int col = nbase + ni * 8 + (lane & 3) * 2;
            __half* p = g_Ch + (size_t)row * Ncols + col;
            *reinterpret_cast<__half2*>(p) =
                make_half2(__float2half_rn(acc[mi][ni][0]),
                           __float2half_rn(acc[mi][ni][1]));
            *reinterpret_cast<__half2*>(p + (size_t)8 * Ncols) =
                make_half2(__float2half_rn(acc[mi][ni][2]),
                           __float2half_rn(acc[mi][ni][3]));
        }
    }
}

// ---------------------------------------------------------------------------
// Kernel 3: per-token epilogue — rmsnorm(q,k), gamma, RoPE, transpose, repeat
// Vectorized: 16B loads, warp-shuffle reduction, streaming float4 stores.
// ---------------------------------------------------------------------------
__device__ __forceinline__ void unpack8(uint4 u, float* f) {
    __half2 h;
    h = *reinterpret_cast<__half2*>(&u.x); f[0] = __low2float(h); f[1] = __high2float(h);
    h = *reinterpret_cast<__half2*>(&u.y); f[2] = __low2float(h); f[3] = __high2float(h);
    h = *reinterpret_cast<__half2*>(&u.z); f[4] = __low2float(h); f[5] = __high2float(h);
    h = *reinterpret_cast<__half2*>(&u.w); f[6] = __low2float(h); f[7] = __high2float(h);
}

__global__ __launch_bounds__(256) void epilogue_kernel(
    const float* __restrict__ gq,
    const float* __restrict__ gk,
    float* __restrict__ out)
{
    const int bt = blockIdx.x;
    const int b = bt >> 12;
    const int t = bt & 4095;
    const __half* row = g_Ch + (size_t)bt * Ncols;
    const int tid = threadIdx.x;
    const int lane = tid & 31;
    const int wid = tid >> 5;

    // ---- loads (vectorized) ----
    float qf[16], kf[4], vf[4];
    {
        const uint4* qp = reinterpret_cast<const uint4*>(row + tid * 16);
        unpack8(qp[0], qf);
        unpack8(qp[1], qf + 8);
        uint2 ku = *reinterpret_cast<const uint2*>(row + 4096 + tid * 4);
        __half2 h;
        h = *reinterpret_cast<__half2*>(&ku.x); kf[0] = __low2float(h); kf[1] = __high2float(h);
        h = *reinterpret_cast<__half2*>(&ku.y); kf[2] = __low2float(h); kf[3] = __high2float(h);
        uint2 vu = *reinterpret_cast<const uint2*>(row + 5120 + tid * 4);
        h = *reinterpret_cast<__half2*>(&vu.x); vf[0] = __low2float(h); vf[1] = __high2float(h);
        h = *reinterpret_cast<__half2*>(&vu.y); vf[2] = __low2float(h); vf[3] = __high2float(h);
    }

    // ---- sums of squares ----
    float ssq_q = 0.0f, ssq_k = 0.0f;
    #pragma unroll
    for (int i = 0; i < 16; i++) ssq_q += qf[i] * qf[i];
    #pragma unroll
    for (int i = 0; i < 4; i++) ssq_k += kf[i] * kf[i];

    #pragma unroll
    for (int o = 16; o > 0; o >>= 1) {
        ssq_q += __shfl_xor_sync(0xFFFFFFFFu, ssq_q, o);
        ssq_k += __shfl_xor_sync(0xFFFFFFFFu, ssq_k, o);
    }
    __shared__ float s_q[8], s_k[8];
    if (lane == 0) { s_q[wid] = ssq_q; s_k[wid] = ssq_k; }
    __syncthreads();
    float tq = 0.0f, tk = 0.0f;
    #pragma unroll
    for (int i = 0; i < 8; i++) { tq += s_q[i]; tk += s_k[i]; }
    const float rs_q = rsqrtf(tq * (1.0f / 4096.0f) + 1e-5f);
    const float rs_k = rsqrtf(tk * (1.0f / 1024.0f) + 1e-5f);

    const float2* tab = g_tab + t * 64;
    float* outq = out;
    float* outk = out + (size_t)33554432;   // B*H*T*DH
    float* outv = out + (size_t)67108864;

    // ---- Q ----
    {
        const int h = tid >> 3;
        const int j0 = (tid * 8) & 63;
        float gqv[16];
        const float4* gp = reinterpret_cast<const float4*>(gq + tid * 16);
        #pragma unroll
        for (int i = 0; i < 4; i++) {
            float4 g4 = gp[i];
            gqv[4 * i] = g4.x; gqv[4 * i + 1] = g4.y;
            gqv[4 * i + 2] = g4.z; gqv[4 * i + 3] = g4.w;
        }
        float r[16];
        #pragma unroll
        for (int i = 0; i < 8; i++) {
            float2 cs = tab[j0 + i];
            float x1 = qf[2 * i] * rs_q * gqv[2 * i];
            float x2 = qf[2 * i + 1] * rs_q * gqv[2 * i + 1];
            r[2 * i]     = x1 * cs.x - x2 * cs.y;
            r[2 * i + 1] = x1 * cs.y + x2 * cs.x;
        }
        float4* dst = reinterpret_cast<float4*>(
            outq + (((size_t)(b * Hh + h) * Tt + t) * DH + 2 * j0));
        #pragma unroll
        for (int i = 0; i < 4; i++)
            __stcs(dst + i, make_float4(r[4 * i], r[4 * i + 1],
                                        r[4 * i + 2], r[4 * i + 3]));
    }

    // ---- K (repeated 4x) ----
    {
        const int kh = tid >> 5;
        const int j0 = (tid * 2) & 63;
        float4 g4 = *reinterpret_cast<const float4*>(gk + tid * 4);
        float2 cs0 = tab[j0];
        float2 cs1 = tab[j0 + 1];
        float x1 = kf[0] * rs_k * g4.x;
        float x2 = kf[1] * rs_k * g4.y;
        float y1 = kf[2] * rs_k * g4.z;
        float y2 = kf[3] * rs_k * g4.w;
        float4 r = make_float4(x1 * cs0.x - x2 * cs0.y, x1 * cs0.y + x2 * cs0.x,
                               y1 * cs1.x - y2 * cs1.y, y1 * cs1.y + y2 * cs1.x);
        #pragma unroll
        for (int rr = 0; rr < 4; rr++) {
            int h = kh * 4 + rr;
            __stcs(reinterpret_cast<float4*>(
                outk + (((size_t)(b * Hh + h) * Tt + t) * DH + 2 * j0)), r);
        }
    }

    // ---- V (repeated 4x) ----
    {
        const int kh = tid >> 5;
        const int d = (tid * 4) & 127;
        float4 r = make_float4(vf[0], vf[1], vf[2], vf[3]);
        #pragma unroll
        for (int rr = 0; rr < 4; rr++) {
            int h = kh * 4 + rr;
            __stcs(reinterpret_cast<float4*>(
                outv + (((size_t)(b * Hh + h) * Tt + t) * DH + d)), r);
        }
    }
}

// ---------------------------------------------------------------------------
extern "C" void kernel_launch(void* const* d_in, const int* in_sizes, int n_in,
                              void* d_out, int out_size)
{
    const float* x  = (const float*)d_in[0];
    const float* Wq = (const float*)d_in[1];
    const float* Wk = (const float*)d_in[2];
    const float* Wv = (const float*)d_in[3];
    const float* gq = (const float*)d_in[4];
    const float* gk = (const float*)d_in[5];
    float* out = (float*)d_out;

    cudaFuncSetAttribute(gemm_kernel,
                         cudaFuncAttributeMaxDynamicSharedMemorySize, SMEM_BYTES);

    prep_kernel<<<RBLOCKS + WBLOCKS + XBLOCKS, 256>>>(x, Wq, Wk, Wv);
    gemm_kernel<<<MT * NT, 256, SMEM_BYTES>>>();
    epilogue_kernel<<<Mrows, 256>>>(gq, gk, out);
}